// round 13
// baseline (speedup 1.0000x reference)
#include <cuda_runtime.h>
#include <cuda_bf16.h>
#include <cstdint>

#define NN 110592
#define CC 128
#define C3 384
#define BB 2
#define GRB 296
#define GEMM_SMEM ((128 * 136 + 2 * 128 * 36) * 4)
#define QK_SMEM ((64 * 136 + 2 * 128 * 20) * 4)

__device__ __nv_bfloat16 g_qkA[(size_t)BB * 256 * NN]; // gemm1 q,k out (bf16)
__device__ float         g_vA [(size_t)BB * CC * NN];  // gemm1 v out (fp32)
__device__ __nv_bfloat16 g_qkB[(size_t)BB * 256 * NN]; // dwconv q,k out (bf16)
__device__ float         g_vB [(size_t)BB * CC * NN];  // dwconv v out (fp32)
__device__ float g_gram[BB * 8 * 16 * 16];
__device__ float g_ssq [BB * 2 * CC];
__device__ float g_W   [BB * CC * CC];

__device__ __forceinline__ unsigned f2tf(float f) {
    unsigned u; asm("cvt.rna.tf32.f32 %0, %1;" : "=r"(u) : "f"(f)); return u;
}
__device__ __forceinline__ float f2tff(float f) { return __uint_as_float(f2tf(f)); }
__device__ __forceinline__ unsigned pbf(float lo, float hi) {
    __nv_bfloat162 h = __floats2bfloat162_rn(lo, hi);
    return *(unsigned*)&h;
}
__device__ __forceinline__ void mma8(float* d, const unsigned* a, const unsigned* b) {
    asm volatile("mma.sync.aligned.m16n8k8.row.col.f32.tf32.tf32.f32 "
                 "{%0,%1,%2,%3}, {%4,%5,%6,%7}, {%8,%9}, {%0,%1,%2,%3};"
                 : "+f"(d[0]), "+f"(d[1]), "+f"(d[2]), "+f"(d[3])
                 : "r"(a[0]), "r"(a[1]), "r"(a[2]), "r"(a[3]), "r"(b[0]), "r"(b[1]));
}
__device__ __forceinline__ void mma16816bf(float* d, const unsigned* a, const unsigned* b) {
    asm volatile("mma.sync.aligned.m16n8k16.row.col.f32.bf16.bf16.f32 "
                 "{%0,%1,%2,%3}, {%4,%5,%6,%7}, {%8,%9}, {%0,%1,%2,%3};"
                 : "+f"(d[0]), "+f"(d[1]), "+f"(d[2]), "+f"(d[3])
                 : "r"(a[0]), "r"(a[1]), "r"(a[2]), "r"(a[3]), "r"(b[0]), "r"(b[1]));
}
__device__ __forceinline__ void ldmx4(unsigned* r, unsigned addr) {
    asm volatile("ldmatrix.sync.aligned.m8n8.x4.shared.b16 {%0,%1,%2,%3}, [%4];"
                 : "=r"(r[0]), "=r"(r[1]), "=r"(r[2]), "=r"(r[3]) : "r"(addr));
}

__global__ void zero_k() {
    int t = blockIdx.x * 256 + threadIdx.x;
    if (t < BB * 8 * 16 * 16) g_gram[t] = 0.f;
    if (t < BB * 2 * CC)      g_ssq[t]  = 0.f;
}

// ------ bf16 GEMM for q,k rows (round-11 proven) --------------------------------
__global__ __launch_bounds__(256, 2) void gemm_qk16(
    const float* __restrict__ A,
    const float* __restrict__ B, long long bBatch,
    __nv_bfloat16* __restrict__ C)
{
    extern __shared__ unsigned smu[];
    unsigned* sB = smu;                // [64][136]
    unsigned* sA = smu + 64 * 136;     // [2][128][20]
    const int tid = threadIdx.x;
    const int bn = blockIdx.x, bb = blockIdx.y;
    const float* Bb = B + (long long)bb * bBatch + (long long)bn * 128;
    __nv_bfloat16* Cb = C + (long long)bb * 256 * NN + (long long)bn * 128;

    {
        const int k2r = tid >> 5, nq = tid & 31;
        #pragma unroll
        for (int g = 0; g < 8; g++) {
            int k2 = g * 8 + k2r;
            const float* r0 = Bb + (long long)(2 * k2) * NN + nq * 4;
            float4 v0 = *(const float4*)r0;
            float4 v1 = *(const float4*)(r0 + NN);
            *(uint4*)&sB[k2 * 136 + nq * 4] = make_uint4(
                pbf(v0.x, v1.x), pbf(v0.y, v1.y), pbf(v0.z, v1.z), pbf(v0.w, v1.w));
        }
    }

    const int ar4 = tid >> 2, aq = tid & 3;
    float4 rgf[4];
    auto ldA = [&](int mt, int kt) {
        const float* At = A + (long long)mt * 16384;
        #pragma unroll
        for (int j = 0; j < 2; j++) {
            const float* p = At + (ar4 + 64 * j) * 128 + kt * 32 + aq * 8;
            rgf[2 * j]     = *(const float4*)p;
            rgf[2 * j + 1] = *(const float4*)(p + 4);
        }
    };
    auto stA = [&](int bufsel) {
        unsigned* base = sA + bufsel * 128 * 20;
        #pragma unroll
        for (int j = 0; j < 2; j++) {
            int m = ar4 + 64 * j;
            float4 u = rgf[2 * j], w = rgf[2 * j + 1];
            *(uint4*)&base[m * 20 + aq * 4] = make_uint4(
                pbf(u.x, u.y), pbf(u.z, u.w), pbf(w.x, w.y), pbf(w.z, w.w));
        }
    };

    ldA(0, 0);
    stA(0);
    __syncthreads();

    const int warp = tid >> 5, lane = tid & 31;
    const int wm = warp >> 2, wn = warp & 3;
    const int lr = lane >> 2, lc = lane & 3;

    int buf = 0;
    float acc[4][4][4];
    for (int step = 0; step < 8; step++) {
        const int mt = step >> 2, kt = step & 3;
        if (kt == 0) {
            #pragma unroll
            for (int a = 0; a < 4; a++)
                #pragma unroll
                for (int b2 = 0; b2 < 4; b2++)
                    #pragma unroll
                    for (int r = 0; r < 4; r++) acc[a][b2][r] = 0.f;
        }
        const bool hasNext = (step + 1 < 8);
        if (hasNext) ldA((step + 1) >> 2, (step + 1) & 3);

        const unsigned* sAb = sA + buf * 128 * 20;
        #pragma unroll
        for (int ks = 0; ks < 2; ks++) {
            const int kq = ks * 8;
            const int k2b = kt * 16 + ks * 8;
            unsigned af[4][4], bfr[4][2];
            #pragma unroll
            for (int mi = 0; mi < 4; mi++) {
                int m0 = wm * 64 + mi * 16;
                af[mi][0] = sAb[(m0 + lr) * 20 + kq + lc];
                af[mi][1] = sAb[(m0 + 8 + lr) * 20 + kq + lc];
                af[mi][2] = sAb[(m0 + lr) * 20 + kq + 4 + lc];
                af[mi][3] = sAb[(m0 + 8 + lr) * 20 + kq + 4 + lc];
            }
            #pragma unroll
            for (int ni = 0; ni < 4; ni++) {
                int n0 = wn * 32 + ni * 8;
                bfr[ni][0] = sB[(k2b + lc) * 136 + n0 + lr];
                bfr[ni][1] = sB[(k2b + 4 + lc) * 136 + n0 + lr];
            }
            #pragma unroll
            for (int mi = 0; mi < 4; mi++)
                #pragma unroll
                for (int ni = 0; ni < 4; ni++)
                    mma16816bf(acc[mi][ni], af[mi], bfr[ni]);
        }
        if (hasNext) stA(buf ^ 1);
        __syncthreads();
        buf ^= 1;

        if (kt == 3) {
            #pragma unroll
            for (int mi = 0; mi < 4; mi++) {
                int m0 = mt * 128 + wm * 64 + mi * 16;
                #pragma unroll
                for (int ni = 0; ni < 4; ni++) {
                    int n0 = wn * 32 + ni * 8;
                    __nv_bfloat162 b0 = __float22bfloat162_rn(
                        make_float2(acc[mi][ni][0], acc[mi][ni][1]));
                    __nv_bfloat162 b1 = __float22bfloat162_rn(
                        make_float2(acc[mi][ni][2], acc[mi][ni][3]));
                    *(__nv_bfloat162*)(Cb + (long long)(m0 + lr) * NN + n0 + lc * 2) = b0;
                    *(__nv_bfloat162*)(Cb + (long long)(m0 + 8 + lr) * NN + n0 + lc * 2) = b1;
                }
            }
        }
    }
}

// ------ TF32 GEMM (round-9 proven) ----------------------------------------------
__global__ __launch_bounds__(256, 2) void gemm_k(
    const float* __restrict__ A, long long aBatch, int MT,
    const float* __restrict__ B, long long bBatch,
    float* __restrict__ Cf)
{
    extern __shared__ float sm[];
    float* sB = sm;
    float* sA = sm + 128 * 136;
    const int tid = threadIdx.x;
    const int bn = blockIdx.x, bb = blockIdx.y;
    const float* Ab = A + (long long)bb * aBatch;
    const float* Bb = B + (long long)bb * bBatch + (long long)bn * 128;
    float* Cf_b = Cf + (long long)bb * (long long)CC * NN + (long long)bn * 128;

    {
        const int r0 = tid >> 5, c4 = tid & 31;
        #pragma unroll
        for (int i = 0; i < 16; i++) {
            int r = i * 8 + r0;
            float4 v = *(const float4*)(Bb + (long long)r * NN + c4 * 4);
            *(float4*)(&sB[r * 136 + c4 * 4]) =
                make_float4(f2tff(v.x), f2tff(v.y), f2tff(v.z), f2tff(v.w));
        }
    }

    const int ar = tid >> 3, ac = tid & 7;
    float4 rg[4];
    auto ldA = [&](int kt) {
        const float* At = Ab + kt * 32;
        #pragma unroll
        for (int j = 0; j < 4; j++)
            rg[j] = *(const float4*)(At + (j * 32 + ar) * 128 + ac * 4);
    };
    auto stA = [&](int bufsel) {
        float* base = sA + bufsel * 128 * 36;
        #pragma unroll
        for (int j = 0; j < 4; j++)
            *(float4*)(base + (j * 32 + ar) * 36 + ac * 4) =
                make_float4(f2tff(rg[j].x), f2tff(rg[j].y), f2tff(rg[j].z), f2tff(rg[j].w));
    };

    ldA(0);
    stA(0);
    __syncthreads();

    const int warp = tid >> 5, lane = tid & 31;
    const int wm = warp >> 2, wn = warp & 3;
    const int lr = lane >> 2, lc = lane & 3;

    int buf = 0;
    float acc[4][4][4];
    #pragma unroll
    for (int a = 0; a < 4; a++)
        #pragma unroll
        for (int b2 = 0; b2 < 4; b2++)
            #pragma unroll
            for (int r = 0; r < 4; r++) acc[a][b2][r] = 0.f;

    for (int kt = 0; kt < 4; kt++) {
        const bool hasNext = (kt + 1 < 4);
        if (hasNext) ldA(kt + 1);

        const float* sAb = sA + buf * 128 * 36;
        #pragma unroll
        for (int ks = 0; ks < 4; ks++) {
            const int k = ks * 8;
            const int kk = kt * 32 + k;
            unsigned af[4][4], bfr[4][2];
            #pragma unroll
            for (int mi = 0; mi < 4; mi++) {
                int m0 = wm * 64 + mi * 16;
                af[mi][0] = __float_as_uint(sAb[(m0 + lr) * 36 + k + lc]);
                af[mi][1] = __float_as_uint(sAb[(m0 + 8 + lr) * 36 + k + lc]);
                af[mi][2] = __float_as_uint(sAb[(m0 + lr) * 36 + k + 4 + lc]);
                af[mi][3] = __float_as_uint(sAb[(m0 + 8 + lr) * 36 + k + 4 + lc]);
            }
            #pragma unroll
            for (int ni = 0; ni < 4; ni++) {
                int n0 = wn * 32 + ni * 8;
                bfr[ni][0] = __float_as_uint(sB[(kk + lc) * 136 + n0 + lr]);
                bfr[ni][1] = __float_as_uint(sB[(kk + 4 + lc) * 136 + n0 + lr]);
            }
            #pragma unroll
            for (int mi = 0; mi < 4; mi++)
                #pragma unroll
                for (int ni = 0; ni < 4; ni++)
                    mma8(acc[mi][ni], af[mi], bfr[ni]);
        }
        if (hasNext) stA(buf ^ 1);
        __syncthreads();
        buf ^= 1;
    }

    #pragma unroll
    for (int mi = 0; mi < 4; mi++) {
        int mloc = wm * 64 + mi * 16;
        #pragma unroll
        for (int ni = 0; ni < 4; ni++) {
            int n0 = wn * 32 + ni * 8;
            long long r0 = (long long)(mloc + lr) * NN + n0 + lc * 2;
            long long r1 = (long long)(mloc + 8 + lr) * NN + n0 + lc * 2;
            *(float2*)(Cf_b + r0) = make_float2(acc[mi][ni][0], acc[mi][ni][1]);
            *(float2*)(Cf_b + r1) = make_float2(acc[mi][ni][2], acc[mi][ni][3]);
        }
    }
}

// ------ depthwise 3x3x3: plane-sweep, each h-plane read ONCE --------------------
// grid (4 = hh*2+wh, 384, BB), threads (48 d, 4 ty of 6 w).
// plane p contributes to out rows p+1 (w-row 0), p (row 1), p-1 (row 2);
// after plane p, out-row p-1 is complete -> emit. 2-plane smem ring [26][60].
__global__ __launch_bounds__(192, 3) void dwconv_k(
    const __nv_bfloat16* __restrict__ qk_in, const float* __restrict__ v_in,
    const float* __restrict__ wg_,
    __nv_bfloat16* __restrict__ qk_out, float* __restrict__ v_out)
{
    __shared__ float sP[2][26 * 60];
    __shared__ float sred[192];
    const int hh = blockIdx.x >> 1, wh = blockIdx.x & 1;
    const int ch = blockIdx.y, b = blockIdx.z;
    const int tx = threadIdx.x, ty = threadIdx.y;
    const int tid = ty * 48 + tx;
    const int h0 = hh * 24;
    const int w0base = wh * 24;
    const bool isQK = (ch < 256);

    for (int i = tid; i < 2 * 1560; i += 192) ((float*)sP)[i] = 0.f;

    float wv[27];
    {
        const float* wp = wg_ + ch * 27;
        #pragma unroll
        for (int i = 0; i < 27; i++) wv[i] = wp[i];
    }
    __syncthreads();

    const __nv_bfloat16* qbase = qk_in + (long long)(b * 256 + ch) * 48 * 2304;
    const float* vbase = v_in + (long long)(b * CC + (ch - 256)) * 48 * 2304;

    auto loadPlane = [&](int slot, int p) {
        float* sp = sP[slot];
        if (p < 0 || p > 47) {
            for (int i = tid; i < 1560; i += 192) sp[i] = 0.f;
            return;
        }
        if (isQK) {
            const __nv_bfloat162* pl = (const __nv_bfloat162*)(qbase + (long long)p * 2304);
            #pragma unroll
            for (int jj = 0; jj < 4; jj++) {
                int idx = jj * 192 + tid;
                if (idx < 624) {
                    int i = idx / 24, cp = idx % 24;
                    int w = w0base - 1 + i;
                    if (w >= 0 && w < 48) {
                        float2 f = __bfloat1622float2(pl[w * 24 + cp]);
                        *(float2*)&sp[i * 60 + 4 + 2 * cp] = f;
                    }
                }
            }
        } else {
            const float* pl = vbase + (long long)p * 2304;
            #pragma unroll
            for (int jj = 0; jj < 2; jj++) {
                int idx = jj * 192 + tid;
                if (idx < 312) {
                    int i = idx / 12, q = idx % 12;
                    int w = w0base - 1 + i;
                    if (w >= 0 && w < 48) {
                        float4 v = *(const float4*)(pl + w * 48 + q * 4);
                        *(float4*)&sp[i * 60 + 4 + 4 * q] = v;
                    }
                }
            }
        }
    };

    loadPlane(0, h0 - 1);
    __syncthreads();

    const int w0 = w0base + ty * 6;
    const int lbase = ty * 6;
    float a0[6], a1[6], a2[6];
    #pragma unroll
    for (int k = 0; k < 6; k++) { a0[k] = 0.f; a1[k] = 0.f; a2[k] = 0.f; }
    float lssq = 0.f;
    __nv_bfloat16* qob0 = qk_out + (long long)(b * 256 + ch) * 48 * 2304;
    float* vob0 = v_out + (long long)(b * CC + (ch - 256)) * 48 * 2304;

    for (int p = h0 - 1; p <= h0 + 24; p++) {
        const int cur = (p - (h0 - 1)) & 1;
        if (p < h0 + 24) loadPlane(cur ^ 1, p + 1);
        const float* sp = sP[cur];

        float r[3][3];  // [w-slot][dp]
        #pragma unroll
        for (int dp = 0; dp < 3; dp++) {
            r[0][dp] = sp[lbase * 60 + tx + 3 + dp];
            r[1][dp] = sp[(lbase + 1) * 60 + tx + 3 + dp];
        }
        #pragma unroll
        for (int k = 0; k < 6; k++) {
            const int ns = (k + 2) % 3;
            #pragma unroll
            for (int dp = 0; dp < 3; dp++)
                r[ns][dp] = sp[(lbase + k + 2) * 60 + tx + 3 + dp];
            float s0 = 0.f, s1 = 0.f, s2 = 0.f;
            #pragma unroll
            for (int q = 0; q < 3; q++) {
                const int sl = (k + q) % 3;
                #pragma unroll
                for (int dp = 0; dp < 3; dp++) {
                    const float tap = r[sl][dp];
                    s0 += wv[0 + q * 3 + dp] * tap;
                    s1 += wv[9 + q * 3 + dp] * tap;
                    s2 += wv[18 + q * 3 + dp] * tap;
                }
            }
            a2[k] += s0;   // out-row p+1 (uses plane p as its hp=0)
            a1[k] += s1;   // out-row p
            a0[k] += s2;   // out-row p-1 (completes)
        }

        if (p - 1 >= h0) {
            const long long rowoff = (long long)(p - 1) * 2304;
            if (isQK) {
                #pragma unroll
                for (int k = 0; k < 6; k++) {
                    __nv_bfloat16 bh = __float2bfloat16_rn(a0[k]);
                    float orr = __bfloat162float(bh);
                    lssq += orr * orr;
                    qob0[rowoff + (w0 + k) * 48 + tx] = bh;
                }
            } else {
                #pragma unroll
                for (int k = 0; k < 6; k++)
                    vob0[rowoff + (w0 + k) * 48 + tx] = a0[k];
            }
        }
        #pragma unroll
        for (int k = 0; k < 6; k++) { a0[k] = a1[k]; a1[k] = a2[k]; a2[k] = 0.f; }
        __syncthreads();
    }

    if (isQK) {
        sred[tid] = lssq;
        __syncthreads();
        if (tid < 32) {
            float v = sred[tid] + sred[tid + 32] + sred[tid + 64]
                    + sred[tid + 96] + sred[tid + 128] + sred[tid + 160];
            #pragma unroll
            for (int off = 16; off > 0; off >>= 1)
                v += __shfl_down_sync(0xffffffffu, v, off);
            if (tid == 0) atomicAdd(&g_ssq[b * 256 + ch], v);
        }
    }
}

// ------ Gram via bf16 tensor cores (round-7 proven) -----------------------------
__global__ __launch_bounds__(256) void gram_k(const __nv_bfloat16* __restrict__ qk) {
    __shared__ __nv_bfloat16 sq[256 * 40];
    const int tid = threadIdx.x;
    const int b = blockIdx.y;
    const int warp = tid >> 5, lane = tid & 31;
    const int lr4 = lane >> 3, lq = lane & 7;
    const __nv_bfloat16* qkb = qk + (long long)b * 256 * NN;

    uint2 rg[8];
    auto ldC = [&](int c) {
        long long n0 = (long long)c * 32;
        #pragma unroll
        for (int j = 0; j < 8; j++) {
            int row = warp * 32 + j * 4 + lr4;
            rg[j] = *(const uint2*)(qkb + (long long)row * NN + n0 + lq * 4);
        }
    };
    auto stC = [&]() {
        #pragma unroll
        for (int j = 0; j < 8; j++) {
            int row = warp * 32 + j * 4 + lr4;
            *(uint2*)(&sq[row * 40 + lq * 4]) = rg[j];
        }
    };

    const int h = warp;
    const int aRow = h * 16 + (lane & 7) + ((lane >> 3) & 1) * 8;
    const unsigned aAddr = (unsigned)__cvta_generic_to_shared(&sq[aRow * 40])
                         + ((lane >> 4) & 1) * 16;
    const int bRow = 128 + h * 16 + (lane & 7) + ((lane >> 4) & 1) * 8;
    const unsigned bAddr = (unsigned)__cvta_generic_to_shared(&sq[bRow * 40])
                         + ((lane >> 3) & 1) * 16;

    float acc[2][4];
    #pragma unroll
    for (int jh = 0; jh < 2; jh++)
        #pragma unroll
        for (int r = 0; r < 4; r++) acc[jh][r] = 0.f;

    int c = blockIdx.x;
    ldC(c);
    while (1) {
        stC();
        __syncthreads();
        int cn = c + GRB;
        bool more = cn < NN / 32;
        if (more) ldC(cn);
        #pragma unroll
        for (int ks = 0; ks < 2; ks++) {
            unsigned a[4], bb2[4];
            ldmx4(a, aAddr + ks * 32);
            ldmx4(bb2, bAddr + ks * 32);
            mma16816bf(acc[0], a, bb2 + 0);
            mma16816bf(acc[1], a, bb2 + 2);
        }
        __syncthreads();
        if (!more) break;
        c = cn;
    }

    const int row = lane >> 2, col = (lane & 3) * 2;
    float* G = &g_gram[(b * 8 + h) * 256];
    #pragma unroll
    for (int jh = 0; jh < 2; jh++) {
        const int j0 = jh * 8 + col;
        atomicAdd(&G[row * 16 + j0],           acc[jh][0]);
        atomicAdd(&G[row * 16 + j0 + 1],       acc[jh][1]);
        atomicAdd(&G[(row + 8) * 16 + j0],     acc[jh][2]);
        atomicAdd(&G[(row + 8) * 16 + j0 + 1], acc[jh][3]);
    }
}

// ------ softmax + W_b = proj_w @ blockdiag(attn_b) ------------------------------
__global__ __launch_bounds__(256) void fold_k(
    const float* __restrict__ proj_w, const float* __restrict__ temp)
{
    __shared__ float sat[8][16][17];
    const int b = blockIdx.x, tid = threadIdx.x;
    if (tid < 128) {
        const int h = tid >> 4, i = tid & 15;
        float nq = fmaxf(sqrtf(g_ssq[b * 256 + h * 16 + i]), 1e-12f);
        float tv = temp[h];
        float row[16];
        float mx = -1e30f;
        #pragma unroll
        for (int j = 0; j < 16; j++) {
            float nk = fmaxf(sqrtf(g_ssq[b * 256 + 128 + h * 16 + j]), 1e-12f);
            float v = g_gram[((b * 8 + h) * 16 + i) * 16 + j] / (nq * nk) * tv;
            row[j] = v;
            mx = fmaxf(mx, v);
        }
        float s = 0.f;
        #pragma unroll
        for (int j = 0; j < 16; j++) { row[j] = expf(row[j] - mx); s += row[j]; }
        const float inv = 1.f / s;
        #pragma unroll
        for (int j = 0; j < 16; j++) sat[h][i][j] = row[j] * inv;
    }
    __syncthreads();
    for (int idx = tid; idx < 16384; idx += 256) {
        const int o = idx >> 7, col = idx & 127;
        const int h = col >> 4, j = col & 15;
        float s = 0.f;
        #pragma unroll
        for (int i = 0; i < 16; i++)
            s += proj_w[o * 128 + h * 16 + i] * sat[h][i][j];
        g_W[b * 16384 + idx] = s;
    }
}

extern "C" void kernel_launch(void* const* d_in, const int* in_sizes, int n_in,
                              void* d_out, int out_size) {
    const float* x      = (const float*)d_in[0];
    const float* qkv_w  = (const float*)d_in[1];
    const float* dw_w   = (const float*)d_in[2];
    const float* proj_w = (const float*)d_in[3];
    const float* temp   = (const float*)d_in[4];
    float* out = (float*)d_out;

    void *p_qkA = nullptr, *p_vA = nullptr, *p_qkB = nullptr, *p_vB = nullptr, *p_W = nullptr;
    cudaGetSymbolAddress(&p_qkA, g_qkA);
    cudaGetSymbolAddress(&p_vA,  g_vA);
    cudaGetSymbolAddress(&p_qkB, g_qkB);
    cudaGetSymbolAddress(&p_vB,  g_vB);
    cudaGetSymbolAddress(&p_W,   g_W);

    cudaFuncSetAttribute(gemm_qk16, cudaFuncAttributeMaxDynamicSharedMemorySize, QK_SMEM);
    cudaFuncSetAttribute(gemm_k,    cudaFuncAttributeMaxDynamicSharedMemorySize, GEMM_SMEM);

    zero_k<<<16, 256>>>();

    // q,k = qkv_w[0:256] @ x  (bf16 MMA, bf16 out)
    gemm_qk16<<<dim3(NN / 128, BB), 256, QK_SMEM>>>(
        qkv_w, x, (long long)CC * NN, (__nv_bfloat16*)p_qkA);

    // v = qkv_w[256:384] @ x  (tf32, fp32 out)
    gemm_k<<<dim3(NN / 128, BB), 256, GEMM_SMEM>>>(
        qkv_w + 256 * 128, 0LL, 1,
        x, (long long)CC * NN,
        (float*)p_vA);

    dwconv_k<<<dim3(4, C3, BB), dim3(48, 4)>>>(
        (const __nv_bfloat16*)p_qkA, (const float*)p_vA, dw_w,
        (__nv_bfloat16*)p_qkB, (float*)p_vB);

    gram_k<<<dim3(GRB, BB), 256>>>((const __nv_bfloat16*)p_qkB);

    fold_k<<<BB, 256>>>(proj_w, temp);

    // out = W_b @ v  (tf32)
    gemm_k<<<dim3(NN / 128, BB), 256, GEMM_SMEM>>>(
        (const float*)p_W, (long long)CC * CC, 1,
        (const float*)p_vB, (long long)CC * NN,
        out);
}

// round 14
// speedup vs baseline: 1.0273x; 1.0273x over previous
#include <cuda_runtime.h>
#include <cuda_bf16.h>
#include <cstdint>

#define NN 110592
#define CC 128
#define C3 384
#define BB 2
#define GRB 296
#define GEMM_SMEM ((128 * 136 + 2 * 128 * 36) * 4)
#define QK_SMEM ((64 * 136 + 2 * 128 * 20) * 4)

__device__ __nv_bfloat16 g_qkA[(size_t)BB * 256 * NN]; // gemm1 q,k out (bf16)
__device__ float         g_vA [(size_t)BB * CC * NN];  // gemm1 v out (fp32)
__device__ __nv_bfloat16 g_qkB[(size_t)BB * 256 * NN]; // dwconv q,k out (bf16)
__device__ float         g_vB [(size_t)BB * CC * NN];  // dwconv v out (fp32)
__device__ float g_gram[BB * 8 * 16 * 16];
__device__ float g_ssq [BB * 2 * CC];
__device__ float g_W   [BB * CC * CC];

__device__ __forceinline__ unsigned f2tf(float f) {
    unsigned u; asm("cvt.rna.tf32.f32 %0, %1;" : "=r"(u) : "f"(f)); return u;
}
__device__ __forceinline__ float f2tff(float f) { return __uint_as_float(f2tf(f)); }
__device__ __forceinline__ unsigned pbf(float lo, float hi) {
    __nv_bfloat162 h = __floats2bfloat162_rn(lo, hi);
    return *(unsigned*)&h;
}
__device__ __forceinline__ void mma8(float* d, const unsigned* a, const unsigned* b) {
    asm volatile("mma.sync.aligned.m16n8k8.row.col.f32.tf32.tf32.f32 "
                 "{%0,%1,%2,%3}, {%4,%5,%6,%7}, {%8,%9}, {%0,%1,%2,%3};"
                 : "+f"(d[0]), "+f"(d[1]), "+f"(d[2]), "+f"(d[3])
                 : "r"(a[0]), "r"(a[1]), "r"(a[2]), "r"(a[3]), "r"(b[0]), "r"(b[1]));
}
__device__ __forceinline__ void mma16816bf(float* d, const unsigned* a, const unsigned* b) {
    asm volatile("mma.sync.aligned.m16n8k16.row.col.f32.bf16.bf16.f32 "
                 "{%0,%1,%2,%3}, {%4,%5,%6,%7}, {%8,%9}, {%0,%1,%2,%3};"
                 : "+f"(d[0]), "+f"(d[1]), "+f"(d[2]), "+f"(d[3])
                 : "r"(a[0]), "r"(a[1]), "r"(a[2]), "r"(a[3]), "r"(b[0]), "r"(b[1]));
}
__device__ __forceinline__ void ldmx4(unsigned* r, unsigned addr) {
    asm volatile("ldmatrix.sync.aligned.m8n8.x4.shared.b16 {%0,%1,%2,%3}, [%4];"
                 : "=r"(r[0]), "=r"(r[1]), "=r"(r[2]), "=r"(r[3]) : "r"(addr));
}

__global__ void zero_k() {
    int t = blockIdx.x * 256 + threadIdx.x;
    if (t < BB * 8 * 16 * 16) g_gram[t] = 0.f;
    if (t < BB * 2 * CC)      g_ssq[t]  = 0.f;
}

// ------ bf16 GEMM for q,k rows (round-11 proven) --------------------------------
__global__ __launch_bounds__(256, 2) void gemm_qk16(
    const float* __restrict__ A,
    const float* __restrict__ B, long long bBatch,
    __nv_bfloat16* __restrict__ C)
{
    extern __shared__ unsigned smu[];
    unsigned* sB = smu;                // [64][136]
    unsigned* sA = smu + 64 * 136;     // [2][128][20]
    const int tid = threadIdx.x;
    const int bn = blockIdx.x, bb = blockIdx.y;
    const float* Bb = B + (long long)bb * bBatch + (long long)bn * 128;
    __nv_bfloat16* Cb = C + (long long)bb * 256 * NN + (long long)bn * 128;

    {
        const int k2r = tid >> 5, nq = tid & 31;
        #pragma unroll
        for (int g = 0; g < 8; g++) {
            int k2 = g * 8 + k2r;
            const float* r0 = Bb + (long long)(2 * k2) * NN + nq * 4;
            float4 v0 = *(const float4*)r0;
            float4 v1 = *(const float4*)(r0 + NN);
            *(uint4*)&sB[k2 * 136 + nq * 4] = make_uint4(
                pbf(v0.x, v1.x), pbf(v0.y, v1.y), pbf(v0.z, v1.z), pbf(v0.w, v1.w));
        }
    }

    const int ar4 = tid >> 2, aq = tid & 3;
    float4 rgf[4];
    auto ldA = [&](int mt, int kt) {
        const float* At = A + (long long)mt * 16384;
        #pragma unroll
        for (int j = 0; j < 2; j++) {
            const float* p = At + (ar4 + 64 * j) * 128 + kt * 32 + aq * 8;
            rgf[2 * j]     = *(const float4*)p;
            rgf[2 * j + 1] = *(const float4*)(p + 4);
        }
    };
    auto stA = [&](int bufsel) {
        unsigned* base = sA + bufsel * 128 * 20;
        #pragma unroll
        for (int j = 0; j < 2; j++) {
            int m = ar4 + 64 * j;
            float4 u = rgf[2 * j], w = rgf[2 * j + 1];
            *(uint4*)&base[m * 20 + aq * 4] = make_uint4(
                pbf(u.x, u.y), pbf(u.z, u.w), pbf(w.x, w.y), pbf(w.z, w.w));
        }
    };

    ldA(0, 0);
    stA(0);
    __syncthreads();

    const int warp = tid >> 5, lane = tid & 31;
    const int wm = warp >> 2, wn = warp & 3;
    const int lr = lane >> 2, lc = lane & 3;

    int buf = 0;
    float acc[4][4][4];
    for (int step = 0; step < 8; step++) {
        const int mt = step >> 2, kt = step & 3;
        if (kt == 0) {
            #pragma unroll
            for (int a = 0; a < 4; a++)
                #pragma unroll
                for (int b2 = 0; b2 < 4; b2++)
                    #pragma unroll
                    for (int r = 0; r < 4; r++) acc[a][b2][r] = 0.f;
        }
        const bool hasNext = (step + 1 < 8);
        if (hasNext) ldA((step + 1) >> 2, (step + 1) & 3);

        const unsigned* sAb = sA + buf * 128 * 20;
        #pragma unroll
        for (int ks = 0; ks < 2; ks++) {
            const int kq = ks * 8;
            const int k2b = kt * 16 + ks * 8;
            unsigned af[4][4], bfr[4][2];
            #pragma unroll
            for (int mi = 0; mi < 4; mi++) {
                int m0 = wm * 64 + mi * 16;
                af[mi][0] = sAb[(m0 + lr) * 20 + kq + lc];
                af[mi][1] = sAb[(m0 + 8 + lr) * 20 + kq + lc];
                af[mi][2] = sAb[(m0 + lr) * 20 + kq + 4 + lc];
                af[mi][3] = sAb[(m0 + 8 + lr) * 20 + kq + 4 + lc];
            }
            #pragma unroll
            for (int ni = 0; ni < 4; ni++) {
                int n0 = wn * 32 + ni * 8;
                bfr[ni][0] = sB[(k2b + lc) * 136 + n0 + lr];
                bfr[ni][1] = sB[(k2b + 4 + lc) * 136 + n0 + lr];
            }
            #pragma unroll
            for (int mi = 0; mi < 4; mi++)
                #pragma unroll
                for (int ni = 0; ni < 4; ni++)
                    mma16816bf(acc[mi][ni], af[mi], bfr[ni]);
        }
        if (hasNext) stA(buf ^ 1);
        __syncthreads();
        buf ^= 1;

        if (kt == 3) {
            #pragma unroll
            for (int mi = 0; mi < 4; mi++) {
                int m0 = mt * 128 + wm * 64 + mi * 16;
                #pragma unroll
                for (int ni = 0; ni < 4; ni++) {
                    int n0 = wn * 32 + ni * 8;
                    __nv_bfloat162 b0 = __float22bfloat162_rn(
                        make_float2(acc[mi][ni][0], acc[mi][ni][1]));
                    __nv_bfloat162 b1 = __float22bfloat162_rn(
                        make_float2(acc[mi][ni][2], acc[mi][ni][3]));
                    *(__nv_bfloat162*)(Cb + (long long)(m0 + lr) * NN + n0 + lc * 2) = b0;
                    *(__nv_bfloat162*)(Cb + (long long)(m0 + 8 + lr) * NN + n0 + lc * 2) = b1;
                }
            }
        }
    }
}

// ------ TF32 GEMM (round-9 proven) ----------------------------------------------
__global__ __launch_bounds__(256, 2) void gemm_k(
    const float* __restrict__ A, long long aBatch, int MT,
    const float* __restrict__ B, long long bBatch,
    float* __restrict__ Cf)
{
    extern __shared__ float sm[];
    float* sB = sm;
    float* sA = sm + 128 * 136;
    const int tid = threadIdx.x;
    const int bn = blockIdx.x, bb = blockIdx.y;
    const float* Ab = A + (long long)bb * aBatch;
    const float* Bb = B + (long long)bb * bBatch + (long long)bn * 128;
    float* Cf_b = Cf + (long long)bb * (long long)CC * NN + (long long)bn * 128;

    {
        const int r0 = tid >> 5, c4 = tid & 31;
        #pragma unroll
        for (int i = 0; i < 16; i++) {
            int r = i * 8 + r0;
            float4 v = *(const float4*)(Bb + (long long)r * NN + c4 * 4);
            *(float4*)(&sB[r * 136 + c4 * 4]) =
                make_float4(f2tff(v.x), f2tff(v.y), f2tff(v.z), f2tff(v.w));
        }
    }

    const int ar = tid >> 3, ac = tid & 7;
    float4 rg[4];
    auto ldA = [&](int kt) {
        const float* At = Ab + kt * 32;
        #pragma unroll
        for (int j = 0; j < 4; j++)
            rg[j] = *(const float4*)(At + (j * 32 + ar) * 128 + ac * 4);
    };
    auto stA = [&](int bufsel) {
        float* base = sA + bufsel * 128 * 36;
        #pragma unroll
        for (int j = 0; j < 4; j++)
            *(float4*)(base + (j * 32 + ar) * 36 + ac * 4) =
                make_float4(f2tff(rg[j].x), f2tff(rg[j].y), f2tff(rg[j].z), f2tff(rg[j].w));
    };

    ldA(0);
    stA(0);
    __syncthreads();

    const int warp = tid >> 5, lane = tid & 31;
    const int wm = warp >> 2, wn = warp & 3;
    const int lr = lane >> 2, lc = lane & 3;

    int buf = 0;
    float acc[4][4][4];
    #pragma unroll
    for (int a = 0; a < 4; a++)
        #pragma unroll
        for (int b2 = 0; b2 < 4; b2++)
            #pragma unroll
            for (int r = 0; r < 4; r++) acc[a][b2][r] = 0.f;

    for (int kt = 0; kt < 4; kt++) {
        const bool hasNext = (kt + 1 < 4);
        if (hasNext) ldA(kt + 1);

        const float* sAb = sA + buf * 128 * 36;
        #pragma unroll
        for (int ks = 0; ks < 4; ks++) {
            const int k = ks * 8;
            const int kk = kt * 32 + k;
            unsigned af[4][4], bfr[4][2];
            #pragma unroll
            for (int mi = 0; mi < 4; mi++) {
                int m0 = wm * 64 + mi * 16;
                af[mi][0] = __float_as_uint(sAb[(m0 + lr) * 36 + k + lc]);
                af[mi][1] = __float_as_uint(sAb[(m0 + 8 + lr) * 36 + k + lc]);
                af[mi][2] = __float_as_uint(sAb[(m0 + lr) * 36 + k + 4 + lc]);
                af[mi][3] = __float_as_uint(sAb[(m0 + 8 + lr) * 36 + k + 4 + lc]);
            }
            #pragma unroll
            for (int ni = 0; ni < 4; ni++) {
                int n0 = wn * 32 + ni * 8;
                bfr[ni][0] = __float_as_uint(sB[(kk + lc) * 136 + n0 + lr]);
                bfr[ni][1] = __float_as_uint(sB[(kk + 4 + lc) * 136 + n0 + lr]);
            }
            #pragma unroll
            for (int mi = 0; mi < 4; mi++)
                #pragma unroll
                for (int ni = 0; ni < 4; ni++)
                    mma8(acc[mi][ni], af[mi], bfr[ni]);
        }
        if (hasNext) stA(buf ^ 1);
        __syncthreads();
        buf ^= 1;
    }

    #pragma unroll
    for (int mi = 0; mi < 4; mi++) {
        int mloc = wm * 64 + mi * 16;
        #pragma unroll
        for (int ni = 0; ni < 4; ni++) {
            int n0 = wn * 32 + ni * 8;
            long long r0 = (long long)(mloc + lr) * NN + n0 + lc * 2;
            long long r1 = (long long)(mloc + 8 + lr) * NN + n0 + lc * 2;
            *(float2*)(Cf_b + r0) = make_float2(acc[mi][ni][0], acc[mi][ni][1]);
            *(float2*)(Cf_b + r1) = make_float2(acc[mi][ni][2], acc[mi][ni][3]);
        }
    }
}

// ------ depthwise 3x3x3 scalar sliding-window (round-11 body, 288-thread blocks) -
// grid (2 h-halves, 384 ch, BB); threads (48 d, 6 w-groups of 8). 4-plane ring.
// regs bind occupancy: 3 blocks/SM = 27 warps (vs 24 at 192x4). smem 48.8KB*3 fits.
__global__ __launch_bounds__(288, 3) void dwconv_k(
    const __nv_bfloat16* __restrict__ qk_in, const float* __restrict__ v_in,
    const float* __restrict__ wg,
    __nv_bfloat16* __restrict__ qk_out, float* __restrict__ v_out)
{
    __shared__ float sP[4][50 * 60];
    __shared__ float sred[288];
    const int hhalf = blockIdx.x, ch = blockIdx.y, b = blockIdx.z;
    const int tx = threadIdx.x, ty = threadIdx.y;
    const int tid = ty * 48 + tx;
    const int h0 = hhalf * 24;
    const bool isQK = (ch < 256);

    for (int i = tid; i < 4 * 3000; i += 288) ((float*)sP)[i] = 0.f;

    float wv[27];
    {
        const float* wp = wg + ch * 27;
        #pragma unroll
        for (int i = 0; i < 27; i++) wv[i] = wp[i];
    }
    __syncthreads();

    const __nv_bfloat16* qbase = qk_in + (long long)(b * 256 + ch) * 48 * 2304;
    const float* vbase = v_in + (long long)(b * CC + (ch - 256)) * 48 * 2304;

    auto loadPlane = [&](int slot, int hh) {
        float* sp = sP[slot];
        if (isQK) {
            const __nv_bfloat162* pl = (const __nv_bfloat162*)(qbase + (long long)hh * 2304);
            #pragma unroll
            for (int j = 0; j < 4; j++) {
                int l = j * 288 + tid;            // pair index 0..1151
                int wr = l / 24, cp = l % 24;
                float2 f = __bfloat1622float2(pl[l]);
                *(float2*)(&sp[(wr + 1) * 60 + 4 + cp * 2]) = f;
            }
        } else {
            const float* pl = vbase + (long long)hh * 2304;
            #pragma unroll
            for (int j = 0; j < 2; j++) {
                int l = j * 288 + tid;            // float4 index 0..575
                int wr = l / 12, q = l % 12;
                float4 v = *(const float4*)(pl + wr * 48 + q * 4);
                *(float4*)(&sp[(wr + 1) * 60 + 4 + q * 4]) = v;
            }
        }
    };
    auto zeroPlane = [&](int slot) {
        float* sp = sP[slot];
        for (int i = tid; i < 3000; i += 288) sp[i] = 0.f;
    };

    if (h0 - 1 >= 0) loadPlane(h0 & 3, h0 - 1);
    loadPlane((h0 + 1) & 3, h0);

    const int d = tx, w0 = ty * 8;
    float lssq = 0.f;
    __nv_bfloat16* qob0 = qk_out + (long long)(b * 256 + ch) * 48 * 2304;
    float* vob0 = v_out + (long long)(b * CC + (ch - 256)) * 48 * 2304;

    for (int h = h0; h < h0 + 24; h++) {
        if (h + 1 < 48) loadPlane((h + 2) & 3, h + 1);
        else            zeroPlane((h + 2) & 3);
        __syncthreads();
        const float* P0 = sP[h & 3];
        const float* P1 = sP[(h + 1) & 3];
        const float* P2 = sP[(h + 2) & 3];

        float r[3][3][3];  // [w-slot][hp][dp]
        #pragma unroll
        for (int dp = 0; dp < 3; dp++) {
            r[0][0][dp] = P0[w0 * 60 + d + 3 + dp];
            r[0][1][dp] = P1[w0 * 60 + d + 3 + dp];
            r[0][2][dp] = P2[w0 * 60 + d + 3 + dp];
            r[1][0][dp] = P0[(w0 + 1) * 60 + d + 3 + dp];
            r[1][1][dp] = P1[(w0 + 1) * 60 + d + 3 + dp];
            r[1][2][dp] = P2[(w0 + 1) * 60 + d + 3 + dp];
        }
        const long long rowoff = (long long)h * 2304;
        #pragma unroll
        for (int k = 0; k < 8; k++) {
            const int ns = (k + 2) % 3;
            #pragma unroll
            for (int dp = 0; dp < 3; dp++) {
                r[ns][0][dp] = P0[(w0 + k + 2) * 60 + d + 3 + dp];
                r[ns][1][dp] = P1[(w0 + k + 2) * 60 + d + 3 + dp];
                r[ns][2][dp] = P2[(w0 + k + 2) * 60 + d + 3 + dp];
            }
            float o = 0.f;
            #pragma unroll
            for (int hp = 0; hp < 3; hp++)
                #pragma unroll
                for (int q = 0; q < 3; q++) {
                    const int sl = (k + q) % 3;
                    #pragma unroll
                    for (int dp = 0; dp < 3; dp++)
                        o += wv[hp * 9 + q * 3 + dp] * r[sl][hp][dp];
                }
            const long long off = rowoff + (w0 + k) * 48 + d;
            if (isQK) {
                __nv_bfloat16 bh = __float2bfloat16_rn(o);
                float orr = __bfloat162float(bh);
                lssq += orr * orr;
                qob0[off] = bh;
            } else {
                vob0[off] = o;
            }
        }
    }

    if (isQK) {
        sred[tid] = lssq;
        __syncthreads();
        if (tid < 32) {
            float v = 0.f;
            #pragma unroll
            for (int j = 0; j < 9; j++) v += sred[tid + j * 32];
            #pragma unroll
            for (int off = 16; off > 0; off >>= 1)
                v += __shfl_down_sync(0xffffffffu, v, off);
            if (tid == 0) atomicAdd(&g_ssq[b * 256 + ch], v);
        }
    }
}

// ------ Gram via bf16 tensor cores (round-7 proven) -----------------------------
__global__ __launch_bounds__(256) void gram_k(const __nv_bfloat16* __restrict__ qk) {
    __shared__ __nv_bfloat16 sq[256 * 40];
    const int tid = threadIdx.x;
    const int b = blockIdx.y;
    const int warp = tid >> 5, lane = tid & 31;
    const int lr4 = lane >> 3, lq = lane & 7;
    const __nv_bfloat16* qkb = qk + (long long)b * 256 * NN;

    uint2 rg[8];
    auto ldC = [&](int c) {
        long long n0 = (long long)c * 32;
        #pragma unroll
        for (int j = 0; j < 8; j++) {
            int row = warp * 32 + j * 4 + lr4;
            rg[j] = *(const uint2*)(qkb + (long long)row * NN + n0 + lq * 4);
        }
    };
    auto stC = [&]() {
        #pragma unroll
        for (int j = 0; j < 8; j++) {
            int row = warp * 32 + j * 4 + lr4;
            *(uint2*)(&sq[row * 40 + lq * 4]) = rg[j];
        }
    };

    const int h = warp;
    const int aRow = h * 16 + (lane & 7) + ((lane >> 3) & 1) * 8;
    const unsigned aAddr = (unsigned)__cvta_generic_to_shared(&sq[aRow * 40])
                         + ((lane >> 4) & 1) * 16;
    const int bRow = 128 + h * 16 + (lane & 7) + ((lane >> 4) & 1) * 8;
    const unsigned bAddr = (unsigned)__cvta_generic_to_shared(&sq[bRow * 40])
                         + ((lane >> 3) & 1) * 16;

    float acc[2][4];
    #pragma unroll
    for (int jh = 0; jh < 2; jh++)
        #pragma unroll
        for (int r = 0; r < 4; r++) acc[jh][r] = 0.f;

    int c = blockIdx.x;
    ldC(c);
    while (1) {
        stC();
        __syncthreads();
        int cn = c + GRB;
        bool more = cn < NN / 32;
        if (more) ldC(cn);
        #pragma unroll
        for (int ks = 0; ks < 2; ks++) {
            unsigned a[4], bb2[4];
            ldmx4(a, aAddr + ks * 32);
            ldmx4(bb2, bAddr + ks * 32);
            mma16816bf(acc[0], a, bb2 + 0);
            mma16816bf(acc[1], a, bb2 + 2);
        }
        __syncthreads();
        if (!more) break;
        c = cn;
    }

    const int row = lane >> 2, col = (lane & 3) * 2;
    float* G = &g_gram[(b * 8 + h) * 256];
    #pragma unroll
    for (int jh = 0; jh < 2; jh++) {
        const int j0 = jh * 8 + col;
        atomicAdd(&G[row * 16 + j0],           acc[jh][0]);
        atomicAdd(&G[row * 16 + j0 + 1],       acc[jh][1]);
        atomicAdd(&G[(row + 8) * 16 + j0],     acc[jh][2]);
        atomicAdd(&G[(row + 8) * 16 + j0 + 1], acc[jh][3]);
    }
}

// ------ softmax + W_b = proj_w @ blockdiag(attn_b) ------------------------------
__global__ __launch_bounds__(256) void fold_k(
    const float* __restrict__ proj_w, const float* __restrict__ temp)
{
    __shared__ float sat[8][16][17];
    const int b = blockIdx.x, tid = threadIdx.x;
    if (tid < 128) {
        const int h = tid >> 4, i = tid & 15;
        float nq = fmaxf(sqrtf(g_ssq[b * 256 + h * 16 + i]), 1e-12f);
        float tv = temp[h];
        float row[16];
        float mx = -1e30f;
        #pragma unroll
        for (int j = 0; j < 16; j++) {
            float nk = fmaxf(sqrtf(g_ssq[b * 256 + 128 + h * 16 + j]), 1e-12f);
            float v = g_gram[((b * 8 + h) * 16 + i) * 16 + j] / (nq * nk) * tv;
            row[j] = v;
            mx = fmaxf(mx, v);
        }
        float s = 0.f;
        #pragma unroll
        for (int j = 0; j < 16; j++) { row[j] = expf(row[j] - mx); s += row[j]; }
        const float inv = 1.f / s;
        #pragma unroll
        for (int j = 0; j < 16; j++) sat[h][i][j] = row[j] * inv;
    }
    __syncthreads();
    for (int idx = tid; idx < 16384; idx += 256) {
        const int o = idx >> 7, col = idx & 127;
        const int h = col >> 4, j = col & 15;
        float s = 0.f;
        #pragma unroll
        for (int i = 0; i < 16; i++)
            s += proj_w[o * 128 + h * 16 + i] * sat[h][i][j];
        g_W[b * 16384 + idx] = s;
    }
}

extern "C" void kernel_launch(void* const* d_in, const int* in_sizes, int n_in,
                              void* d_out, int out_size) {
    const float* x      = (const float*)d_in[0];
    const float* qkv_w  = (const float*)d_in[1];
    const float* dw_w   = (const float*)d_in[2];
    const float* proj_w = (const float*)d_in[3];
    const float* temp   = (const float*)d_in[4];
    float* out = (float*)d_out;

    void *p_qkA = nullptr, *p_vA = nullptr, *p_qkB = nullptr, *p_vB = nullptr, *p_W = nullptr;
    cudaGetSymbolAddress(&p_qkA, g_qkA);
    cudaGetSymbolAddress(&p_vA,  g_vA);
    cudaGetSymbolAddress(&p_qkB, g_qkB);
    cudaGetSymbolAddress(&p_vB,  g_vB);
    cudaGetSymbolAddress(&p_W,   g_W);

    cudaFuncSetAttribute(gemm_qk16, cudaFuncAttributeMaxDynamicSharedMemorySize, QK_SMEM);
    cudaFuncSetAttribute(gemm_k,    cudaFuncAttributeMaxDynamicSharedMemorySize, GEMM_SMEM);

    zero_k<<<16, 256>>>();

    // q,k = qkv_w[0:256] @ x  (bf16 MMA, bf16 out)
    gemm_qk16<<<dim3(NN / 128, BB), 256, QK_SMEM>>>(
        qkv_w, x, (long long)CC * NN, (__nv_bfloat16*)p_qkA);

    // v = qkv_w[256:384] @ x  (tf32, fp32 out)
    gemm_k<<<dim3(NN / 128, BB), 256, GEMM_SMEM>>>(
        qkv_w + 256 * 128, 0LL, 1,
        x, (long long)CC * NN,
        (float*)p_vA);

    dwconv_k<<<dim3(2, C3, BB), dim3(48, 6)>>>(
        (const __nv_bfloat16*)p_qkA, (const float*)p_vA, dw_w,
        (__nv_bfloat16*)p_qkB, (float*)p_vB);

    gram_k<<<dim3(GRB, BB), 256>>>((const __nv_bfloat16*)p_qkB);

    fold_k<<<BB, 256>>>(proj_w, temp);

    // out = W_b @ v  (tf32)
    gemm_k<<<dim3(NN / 128, BB), 256, GEMM_SMEM>>>(
        (const float*)p_W, (long long)CC * CC, 1,
        (const float*)p_vB, (long long)CC * NN,
        out);
}

// round 15
// speedup vs baseline: 1.1487x; 1.1182x over previous
#include <cuda_runtime.h>
#include <cuda_bf16.h>
#include <cuda_fp16.h>
#include <cstdint>

#define NN 110592
#define CC 128
#define C3 384
#define BB 2
#define GRB 296
#define GEMM_SMEM ((128 * 136 + 2 * 128 * 36) * 4)
#define QK_SMEM ((64 * 136 + 2 * 128 * 20) * 4)

__device__ __nv_bfloat16 g_qkA[(size_t)BB * 256 * NN]; // gemm1 q,k out (bf16)
__device__ __half        g_vA [(size_t)BB * CC * NN];  // gemm1 v out (fp16)
__device__ __nv_bfloat16 g_qkB[(size_t)BB * 256 * NN]; // dwconv q,k out (bf16)
__device__ __half        g_vB [(size_t)BB * CC * NN];  // dwconv v out (fp16)
__device__ float g_gram[BB * 8 * 16 * 16];
__device__ float g_ssq [BB * 2 * CC];
__device__ float g_W   [BB * CC * CC];

__device__ __forceinline__ unsigned f2tf(float f) {
    unsigned u; asm("cvt.rna.tf32.f32 %0, %1;" : "=r"(u) : "f"(f)); return u;
}
__device__ __forceinline__ float f2tff(float f) { return __uint_as_float(f2tf(f)); }
__device__ __forceinline__ unsigned pbf(float lo, float hi) {
    __nv_bfloat162 h = __floats2bfloat162_rn(lo, hi);
    return *(unsigned*)&h;
}
__device__ __forceinline__ void mma8(float* d, const unsigned* a, const unsigned* b) {
    asm volatile("mma.sync.aligned.m16n8k8.row.col.f32.tf32.tf32.f32 "
                 "{%0,%1,%2,%3}, {%4,%5,%6,%7}, {%8,%9}, {%0,%1,%2,%3};"
                 : "+f"(d[0]), "+f"(d[1]), "+f"(d[2]), "+f"(d[3])
                 : "r"(a[0]), "r"(a[1]), "r"(a[2]), "r"(a[3]), "r"(b[0]), "r"(b[1]));
}
__device__ __forceinline__ void mma16816bf(float* d, const unsigned* a, const unsigned* b) {
    asm volatile("mma.sync.aligned.m16n8k16.row.col.f32.bf16.bf16.f32 "
                 "{%0,%1,%2,%3}, {%4,%5,%6,%7}, {%8,%9}, {%0,%1,%2,%3};"
                 : "+f"(d[0]), "+f"(d[1]), "+f"(d[2]), "+f"(d[3])
                 : "r"(a[0]), "r"(a[1]), "r"(a[2]), "r"(a[3]), "r"(b[0]), "r"(b[1]));
}
__device__ __forceinline__ void ldmx4(unsigned* r, unsigned addr) {
    asm volatile("ldmatrix.sync.aligned.m8n8.x4.shared.b16 {%0,%1,%2,%3}, [%4];"
                 : "=r"(r[0]), "=r"(r[1]), "=r"(r[2]), "=r"(r[3]) : "r"(addr));
}

__global__ void zero_k() {
    int t = blockIdx.x * 256 + threadIdx.x;
    if (t < BB * 8 * 16 * 16) g_gram[t] = 0.f;
    if (t < BB * 2 * CC)      g_ssq[t]  = 0.f;
}

// ------ bf16 GEMM for q,k rows (round-11 proven) --------------------------------
__global__ __launch_bounds__(256, 2) void gemm_qk16(
    const float* __restrict__ A,
    const float* __restrict__ B, long long bBatch,
    __nv_bfloat16* __restrict__ C)
{
    extern __shared__ unsigned smu[];
    unsigned* sB = smu;                // [64][136]
    unsigned* sA = smu + 64 * 136;     // [2][128][20]
    const int tid = threadIdx.x;
    const int bn = blockIdx.x, bb = blockIdx.y;
    const float* Bb = B + (long long)bb * bBatch + (long long)bn * 128;
    __nv_bfloat16* Cb = C + (long long)bb * 256 * NN + (long long)bn * 128;

    {
        const int k2r = tid >> 5, nq = tid & 31;
        #pragma unroll
        for (int g = 0; g < 8; g++) {
            int k2 = g * 8 + k2r;
            const float* r0 = Bb + (long long)(2 * k2) * NN + nq * 4;
            float4 v0 = *(const float4*)r0;
            float4 v1 = *(const float4*)(r0 + NN);
            *(uint4*)&sB[k2 * 136 + nq * 4] = make_uint4(
                pbf(v0.x, v1.x), pbf(v0.y, v1.y), pbf(v0.z, v1.z), pbf(v0.w, v1.w));
        }
    }

    const int ar4 = tid >> 2, aq = tid & 3;
    float4 rgf[4];
    auto ldA = [&](int mt, int kt) {
        const float* At = A + (long long)mt * 16384;
        #pragma unroll
        for (int j = 0; j < 2; j++) {
            const float* p = At + (ar4 + 64 * j) * 128 + kt * 32 + aq * 8;
            rgf[2 * j]     = *(const float4*)p;
            rgf[2 * j + 1] = *(const float4*)(p + 4);
        }
    };
    auto stA = [&](int bufsel) {
        unsigned* base = sA + bufsel * 128 * 20;
        #pragma unroll
        for (int j = 0; j < 2; j++) {
            int m = ar4 + 64 * j;
            float4 u = rgf[2 * j], w = rgf[2 * j + 1];
            *(uint4*)&base[m * 20 + aq * 4] = make_uint4(
                pbf(u.x, u.y), pbf(u.z, u.w), pbf(w.x, w.y), pbf(w.z, w.w));
        }
    };

    ldA(0, 0);
    stA(0);
    __syncthreads();

    const int warp = tid >> 5, lane = tid & 31;
    const int wm = warp >> 2, wn = warp & 3;
    const int lr = lane >> 2, lc = lane & 3;

    int buf = 0;
    float acc[4][4][4];
    for (int step = 0; step < 8; step++) {
        const int mt = step >> 2, kt = step & 3;
        if (kt == 0) {
            #pragma unroll
            for (int a = 0; a < 4; a++)
                #pragma unroll
                for (int b2 = 0; b2 < 4; b2++)
                    #pragma unroll
                    for (int r = 0; r < 4; r++) acc[a][b2][r] = 0.f;
        }
        const bool hasNext = (step + 1 < 8);
        if (hasNext) ldA((step + 1) >> 2, (step + 1) & 3);

        const unsigned* sAb = sA + buf * 128 * 20;
        #pragma unroll
        for (int ks = 0; ks < 2; ks++) {
            const int kq = ks * 8;
            const int k2b = kt * 16 + ks * 8;
            unsigned af[4][4], bfr[4][2];
            #pragma unroll
            for (int mi = 0; mi < 4; mi++) {
                int m0 = wm * 64 + mi * 16;
                af[mi][0] = sAb[(m0 + lr) * 20 + kq + lc];
                af[mi][1] = sAb[(m0 + 8 + lr) * 20 + kq + lc];
                af[mi][2] = sAb[(m0 + lr) * 20 + kq + 4 + lc];
                af[mi][3] = sAb[(m0 + 8 + lr) * 20 + kq + 4 + lc];
            }
            #pragma unroll
            for (int ni = 0; ni < 4; ni++) {
                int n0 = wn * 32 + ni * 8;
                bfr[ni][0] = sB[(k2b + lc) * 136 + n0 + lr];
                bfr[ni][1] = sB[(k2b + 4 + lc) * 136 + n0 + lr];
            }
            #pragma unroll
            for (int mi = 0; mi < 4; mi++)
                #pragma unroll
                for (int ni = 0; ni < 4; ni++)
                    mma16816bf(acc[mi][ni], af[mi], bfr[ni]);
        }
        if (hasNext) stA(buf ^ 1);
        __syncthreads();
        buf ^= 1;

        if (kt == 3) {
            #pragma unroll
            for (int mi = 0; mi < 4; mi++) {
                int m0 = mt * 128 + wm * 64 + mi * 16;
                #pragma unroll
                for (int ni = 0; ni < 4; ni++) {
                    int n0 = wn * 32 + ni * 8;
                    __nv_bfloat162 b0 = __float22bfloat162_rn(
                        make_float2(acc[mi][ni][0], acc[mi][ni][1]));
                    __nv_bfloat162 b1 = __float22bfloat162_rn(
                        make_float2(acc[mi][ni][2], acc[mi][ni][3]));
                    *(__nv_bfloat162*)(Cb + (long long)(m0 + lr) * NN + n0 + lc * 2) = b0;
                    *(__nv_bfloat162*)(Cb + (long long)(m0 + 8 + lr) * NN + n0 + lc * 2) = b1;
                }
            }
        }
    }
}

// ------ TF32 GEMM (round-9 proven core). TB: B element type; TC: C element type --
template <typename TB, typename TC>
__global__ __launch_bounds__(256, 2) void gemm_k(
    const float* __restrict__ A, long long aBatch, int MT,
    const TB* __restrict__ B, long long bBatch,
    TC* __restrict__ Cf)
{
    extern __shared__ float sm[];
    float* sB = sm;
    float* sA = sm + 128 * 136;
    const int tid = threadIdx.x;
    const int bn = blockIdx.x, bb = blockIdx.y;
    const float* Ab = A + (long long)bb * aBatch;
    const TB* Bb = B + (long long)bb * bBatch + (long long)bn * 128;
    TC* Cf_b = Cf + (long long)bb * (long long)CC * NN + (long long)bn * 128;

    {
        const int r0 = tid >> 5, c4 = tid & 31;
        #pragma unroll
        for (int i = 0; i < 16; i++) {
            int r = i * 8 + r0;
            if constexpr (sizeof(TB) == 4) {
                float4 v = *(const float4*)((const float*)Bb + (long long)r * NN + c4 * 4);
                *(float4*)(&sB[r * 136 + c4 * 4]) =
                    make_float4(f2tff(v.x), f2tff(v.y), f2tff(v.z), f2tff(v.w));
            } else {
                const __half2* hp = (const __half2*)((const __half*)Bb + (long long)r * NN + c4 * 4);
                float2 lo = __half22float2(hp[0]);
                float2 hi = __half22float2(hp[1]);
                *(float4*)(&sB[r * 136 + c4 * 4]) =
                    make_float4(f2tff(lo.x), f2tff(lo.y), f2tff(hi.x), f2tff(hi.y));
            }
        }
    }

    const int ar = tid >> 3, ac = tid & 7;
    float4 rg[4];
    auto ldA = [&](int kt) {
        const float* At = Ab + kt * 32;
        #pragma unroll
        for (int j = 0; j < 4; j++)
            rg[j] = *(const float4*)(At + (j * 32 + ar) * 128 + ac * 4);
    };
    auto stA = [&](int bufsel) {
        float* base = sA + bufsel * 128 * 36;
        #pragma unroll
        for (int j = 0; j < 4; j++)
            *(float4*)(base + (j * 32 + ar) * 36 + ac * 4) =
                make_float4(f2tff(rg[j].x), f2tff(rg[j].y), f2tff(rg[j].z), f2tff(rg[j].w));
    };

    ldA(0);
    stA(0);
    __syncthreads();

    const int warp = tid >> 5, lane = tid & 31;
    const int wm = warp >> 2, wn = warp & 3;
    const int lr = lane >> 2, lc = lane & 3;

    int buf = 0;
    float acc[4][4][4];
    #pragma unroll
    for (int a = 0; a < 4; a++)
        #pragma unroll
        for (int b2 = 0; b2 < 4; b2++)
            #pragma unroll
            for (int r = 0; r < 4; r++) acc[a][b2][r] = 0.f;

    for (int kt = 0; kt < 4; kt++) {
        const bool hasNext = (kt + 1 < 4);
        if (hasNext) ldA(kt + 1);

        const float* sAb = sA + buf * 128 * 36;
        #pragma unroll
        for (int ks = 0; ks < 4; ks++) {
            const int k = ks * 8;
            const int kk = kt * 32 + k;
            unsigned af[4][4], bfr[4][2];
            #pragma unroll
            for (int mi = 0; mi < 4; mi++) {
                int m0 = wm * 64 + mi * 16;
                af[mi][0] = __float_as_uint(sAb[(m0 + lr) * 36 + k + lc]);
                af[mi][1] = __float_as_uint(sAb[(m0 + 8 + lr) * 36 + k + lc]);
                af[mi][2] = __float_as_uint(sAb[(m0 + lr) * 36 + k + 4 + lc]);
                af[mi][3] = __float_as_uint(sAb[(m0 + 8 + lr) * 36 + k + 4 + lc]);
            }
            #pragma unroll
            for (int ni = 0; ni < 4; ni++) {
                int n0 = wn * 32 + ni * 8;
                bfr[ni][0] = __float_as_uint(sB[(kk + lc) * 136 + n0 + lr]);
                bfr[ni][1] = __float_as_uint(sB[(kk + 4 + lc) * 136 + n0 + lr]);
            }
            #pragma unroll
            for (int mi = 0; mi < 4; mi++)
                #pragma unroll
                for (int ni = 0; ni < 4; ni++)
                    mma8(acc[mi][ni], af[mi], bfr[ni]);
        }
        if (hasNext) stA(buf ^ 1);
        __syncthreads();
        buf ^= 1;
    }

    #pragma unroll
    for (int mi = 0; mi < 4; mi++) {
        int mloc = wm * 64 + mi * 16;
        #pragma unroll
        for (int ni = 0; ni < 4; ni++) {
            int n0 = wn * 32 + ni * 8;
            long long r0 = (long long)(mloc + lr) * NN + n0 + lc * 2;
            long long r1 = (long long)(mloc + 8 + lr) * NN + n0 + lc * 2;
            if constexpr (sizeof(TC) == 4) {
                *(float2*)((float*)Cf_b + r0) = make_float2(acc[mi][ni][0], acc[mi][ni][1]);
                *(float2*)((float*)Cf_b + r1) = make_float2(acc[mi][ni][2], acc[mi][ni][3]);
            } else {
                *(__half2*)((__half*)Cf_b + r0) =
                    __floats2half2_rn(acc[mi][ni][0], acc[mi][ni][1]);
                *(__half2*)((__half*)Cf_b + r1) =
                    __floats2half2_rn(acc[mi][ni][2], acc[mi][ni][3]);
            }
        }
    }
}

// ------ depthwise 3x3x3 scalar sliding-window (round-11 proven, v path fp16) ----
__global__ __launch_bounds__(192, 4) void dwconv_k(
    const __nv_bfloat16* __restrict__ qk_in, const __half* __restrict__ v_in,
    const float* __restrict__ wg,
    __nv_bfloat16* __restrict__ qk_out, __half* __restrict__ v_out)
{
    __shared__ float sP[4][50 * 60];
    __shared__ float sred[192];
    const int hhalf = blockIdx.x, ch = blockIdx.y, b = blockIdx.z;
    const int tx = threadIdx.x, ty = threadIdx.y;
    const int tid = ty * 48 + tx;
    const int h0 = hhalf * 24;
    const bool isQK = (ch < 256);

    for (int i = tid; i < 4 * 3000; i += 192) ((float*)sP)[i] = 0.f;

    float wv[27];
    {
        const float* wp = wg + ch * 27;
        #pragma unroll
        for (int i = 0; i < 27; i++) wv[i] = wp[i];
    }
    __syncthreads();

    const __nv_bfloat16* qbase = qk_in + (long long)(b * 256 + ch) * 48 * 2304;
    const __half* vbase = v_in + (long long)(b * CC + (ch - 256)) * 48 * 2304;

    auto loadPlane = [&](int slot, int hh) {
        float* sp = sP[slot];
        if (isQK) {
            const __nv_bfloat162* pl = (const __nv_bfloat162*)(qbase + (long long)hh * 2304);
            #pragma unroll
            for (int j = 0; j < 6; j++) {
                int l = j * 192 + tid;
                int wr = l / 24, cp = l % 24;
                float2 f = __bfloat1622float2(pl[l]);
                *(float2*)(&sp[(wr + 1) * 60 + 4 + cp * 2]) = f;
            }
        } else {
            const __half2* pl = (const __half2*)(vbase + (long long)hh * 2304);
            #pragma unroll
            for (int j = 0; j < 6; j++) {
                int l = j * 192 + tid;
                int wr = l / 24, cp = l % 24;
                float2 f = __half22float2(pl[l]);
                *(float2*)(&sp[(wr + 1) * 60 + 4 + cp * 2]) = f;
            }
        }
    };
    auto zeroPlane = [&](int slot) {
        float* sp = sP[slot];
        for (int i = tid; i < 3000; i += 192) sp[i] = 0.f;
    };

    if (h0 - 1 >= 0) loadPlane(h0 & 3, h0 - 1);
    loadPlane((h0 + 1) & 3, h0);

    const int d = tx, w0 = ty * 12;
    float lssq = 0.f;
    __nv_bfloat16* qob0 = qk_out + (long long)(b * 256 + ch) * 48 * 2304;
    __half* vob0 = v_out + (long long)(b * CC + (ch - 256)) * 48 * 2304;

    for (int h = h0; h < h0 + 24; h++) {
        if (h + 1 < 48) loadPlane((h + 2) & 3, h + 1);
        else            zeroPlane((h + 2) & 3);
        __syncthreads();
        const float* P0 = sP[h & 3];
        const float* P1 = sP[(h + 1) & 3];
        const float* P2 = sP[(h + 2) & 3];

        float r[3][3][3];
        #pragma unroll
        for (int dp = 0; dp < 3; dp++) {
            r[0][0][dp] = P0[w0 * 60 + d + 3 + dp];
            r[0][1][dp] = P1[w0 * 60 + d + 3 + dp];
            r[0][2][dp] = P2[w0 * 60 + d + 3 + dp];
            r[1][0][dp] = P0[(w0 + 1) * 60 + d + 3 + dp];
            r[1][1][dp] = P1[(w0 + 1) * 60 + d + 3 + dp];
            r[1][2][dp] = P2[(w0 + 1) * 60 + d + 3 + dp];
        }
        const long long rowoff = (long long)h * 2304;
        #pragma unroll
        for (int k = 0; k < 12; k++) {
            const int ns = (k + 2) % 3;
            #pragma unroll
            for (int dp = 0; dp < 3; dp++) {
                r[ns][0][dp] = P0[(w0 + k + 2) * 60 + d + 3 + dp];
                r[ns][1][dp] = P1[(w0 + k + 2) * 60 + d + 3 + dp];
                r[ns][2][dp] = P2[(w0 + k + 2) * 60 + d + 3 + dp];
            }
            float o = 0.f;
            #pragma unroll
            for (int hp = 0; hp < 3; hp++)
                #pragma unroll
                for (int q = 0; q < 3; q++) {
                    const int sl = (k + q) % 3;
                    #pragma unroll
                    for (int dp = 0; dp < 3; dp++)
                        o += wv[hp * 9 + q * 3 + dp] * r[sl][hp][dp];
                }
            const long long off = rowoff + (w0 + k) * 48 + d;
            if (isQK) {
                __nv_bfloat16 bh = __float2bfloat16_rn(o);
                float orr = __bfloat162float(bh);
                lssq += orr * orr;
                qob0[off] = bh;
            } else {
                vob0[off] = __float2half_rn(o);
            }
        }
    }

    if (isQK) {
        sred[tid] = lssq;
        __syncthreads();
        if (tid < 32) {
            float v = sred[tid] + sred[tid + 32] + sred[tid + 64]
                    + sred[tid + 96] + sred[tid + 128] + sred[tid + 160];
            #pragma unroll
            for (int off = 16; off > 0; off >>= 1)
                v += __shfl_down_sync(0xffffffffu, v, off);
            if (tid == 0) atomicAdd(&g_ssq[b * 256 + ch], v);
        }
    }
}

// ------ Gram via bf16 tensor cores (round-7 proven) -----------------------------
__global__ __launch_bounds__(256) void gram_k(const __nv_bfloat16* __restrict__ qk) {
    __shared__ __nv_bfloat16 sq[256 * 40];
    const int tid = threadIdx.x;
    const int b = blockIdx.y;
    const int warp = tid >> 5, lane = tid & 31;
    const int lr4 = lane >> 3, lq = lane & 7;
    const __nv_bfloat16* qkb = qk + (long long)b * 256 * NN;

    uint2 rg[8];
    auto ldC = [&](int c) {
        long long n0 = (long long)c * 32;
        #pragma unroll
        for (int j = 0; j < 8; j++) {
            int row = warp * 32 + j * 4 + lr4;
            rg[j] = *(const uint2*)(qkb + (long long)row * NN + n0 + lq * 4);
        }
    };
    auto stC = [&]() {
        #pragma unroll
        for (int j = 0; j < 8; j++) {
            int row = warp * 32 + j * 4 + lr4;
            *(uint2*)(&sq[row * 40 + lq * 4]) = rg[j];
        }
    };

    const int h = warp;
    const int aRow = h * 16 + (lane & 7) + ((lane >> 3) & 1) * 8;
    const unsigned aAddr = (unsigned)__cvta_generic_to_shared(&sq[aRow * 40])
                         + ((lane >> 4) & 1) * 16;
    const int bRow = 128 + h * 16 + (lane & 7) + ((lane >> 4) & 1) * 8;
    const unsigned bAddr = (unsigned)__cvta_generic_to_shared(&sq[bRow * 40])
                         + ((lane >> 3) & 1) * 16;

    float acc[2][4];
    #pragma unroll
    for (int jh = 0; jh < 2; jh++)
        #pragma unroll
        for (int r = 0; r < 4; r++) acc[jh][r] = 0.f;

    int c = blockIdx.x;
    ldC(c);
    while (1) {
        stC();
        __syncthreads();
        int cn = c + GRB;
        bool more = cn < NN / 32;
        if (more) ldC(cn);
        #pragma unroll
        for (int ks = 0; ks < 2; ks++) {
            unsigned a[4], bb2[4];
            ldmx4(a, aAddr + ks * 32);
            ldmx4(bb2, bAddr + ks * 32);
            mma16816bf(acc[0], a, bb2 + 0);
            mma16816bf(acc[1], a, bb2 + 2);
        }
        __syncthreads();
        if (!more) break;
        c = cn;
    }

    const int row = lane >> 2, col = (lane & 3) * 2;
    float* G = &g_gram[(b * 8 + h) * 256];
    #pragma unroll
    for (int jh = 0; jh < 2; jh++) {
        const int j0 = jh * 8 + col;
        atomicAdd(&G[row * 16 + j0],           acc[jh][0]);
        atomicAdd(&G[row * 16 + j0 + 1],       acc[jh][1]);
        atomicAdd(&G[(row + 8) * 16 + j0],     acc[jh][2]);
        atomicAdd(&G[(row + 8) * 16 + j0 + 1], acc[jh][3]);
    }
}

// ------ softmax + W_b = proj_w @ blockdiag(attn_b) ------------------------------
__global__ __launch_bounds__(256) void fold_k(
    const float* __restrict__ proj_w, const float* __restrict__ temp)
{
    __shared__ float sat[8][16][17];
    const int b = blockIdx.x, tid = threadIdx.x;
    if (tid < 128) {
        const int h = tid >> 4, i = tid & 15;
        float nq = fmaxf(sqrtf(g_ssq[b * 256 + h * 16 + i]), 1e-12f);
        float tv = temp[h];
        float row[16];
        float mx = -1e30f;
        #pragma unroll
        for (int j = 0; j < 16; j++) {
            float nk = fmaxf(sqrtf(g_ssq[b * 256 + 128 + h * 16 + j]), 1e-12f);
            float v = g_gram[((b * 8 + h) * 16 + i) * 16 + j] / (nq * nk) * tv;
            row[j] = v;
            mx = fmaxf(mx, v);
        }
        float s = 0.f;
        #pragma unroll
        for (int j = 0; j < 16; j++) { row[j] = expf(row[j] - mx); s += row[j]; }
        const float inv = 1.f / s;
        #pragma unroll
        for (int j = 0; j < 16; j++) sat[h][i][j] = row[j] * inv;
    }
    __syncthreads();
    for (int idx = tid; idx < 16384; idx += 256) {
        const int o = idx >> 7, col = idx & 127;
        const int h = col >> 4, j = col & 15;
        float s = 0.f;
        #pragma unroll
        for (int i = 0; i < 16; i++)
            s += proj_w[o * 128 + h * 16 + i] * sat[h][i][j];
        g_W[b * 16384 + idx] = s;
    }
}

extern "C" void kernel_launch(void* const* d_in, const int* in_sizes, int n_in,
                              void* d_out, int out_size) {
    const float* x      = (const float*)d_in[0];
    const float* qkv_w  = (const float*)d_in[1];
    const float* dw_w   = (const float*)d_in[2];
    const float* proj_w = (const float*)d_in[3];
    const float* temp   = (const float*)d_in[4];
    float* out = (float*)d_out;

    void *p_qkA = nullptr, *p_vA = nullptr, *p_qkB = nullptr, *p_vB = nullptr, *p_W = nullptr;
    cudaGetSymbolAddress(&p_qkA, g_qkA);
    cudaGetSymbolAddress(&p_vA,  g_vA);
    cudaGetSymbolAddress(&p_qkB, g_qkB);
    cudaGetSymbolAddress(&p_vB,  g_vB);
    cudaGetSymbolAddress(&p_W,   g_W);

    cudaFuncSetAttribute(gemm_qk16, cudaFuncAttributeMaxDynamicSharedMemorySize, QK_SMEM);
    cudaFuncSetAttribute((gemm_k<float, __half>),  cudaFuncAttributeMaxDynamicSharedMemorySize, GEMM_SMEM);
    cudaFuncSetAttribute((gemm_k<__half, float>),  cudaFuncAttributeMaxDynamicSharedMemorySize, GEMM_SMEM);

    zero_k<<<16, 256>>>();

    // q,k = qkv_w[0:256] @ x  (bf16 MMA, bf16 out)
    gemm_qk16<<<dim3(NN / 128, BB), 256, QK_SMEM>>>(
        qkv_w, x, (long long)CC * NN, (__nv_bfloat16*)p_qkA);

    // v = qkv_w[256:384] @ x  (tf32, fp16 out)
    gemm_k<float, __half><<<dim3(NN / 128, BB), 256, GEMM_SMEM>>>(
        qkv_w + 256 * 128, 0LL, 1,
        x, (long long)CC * NN,
        (__half*)p_vA);

    dwconv_k<<<dim3(2, C3, BB), dim3(48, 4)>>>(
        (const __nv_bfloat16*)p_qkA, (const __half*)p_vA, dw_w,
        (__nv_bfloat16*)p_qkB, (__half*)p_vB);

    gram_k<<<dim3(GRB, BB), 256>>>((const __nv_bfloat16*)p_qkB);

    fold_k<<<BB, 256>>>(proj_w, temp);

    // out = W_b @ v  (tf32, fp16 B in, fp32 out)
    gemm_k<__half, float><<<dim3(NN / 128, BB), 256, GEMM_SMEM>>>(
        (const float*)p_W, (long long)CC * CC, 1,
        (const __half*)p_vB, (long long)CC * NN,
        out);
}

// round 16
// speedup vs baseline: 1.2725x; 1.1077x over previous
#include <cuda_runtime.h>
#include <cuda_bf16.h>
#include <cuda_fp16.h>
#include <cstdint>

#define NN 110592
#define CC 128
#define C3 384
#define BB 2
#define GRB 296
#define QK_SMEM ((64 * 136 + 2 * 128 * 20) * 4)

__device__ __nv_bfloat16 g_qkA[(size_t)BB * 256 * NN]; // gemm1 q,k out (bf16)
__device__ __half        g_vA [(size_t)BB * CC * NN];  // gemm1 v out (fp16)
__device__ __nv_bfloat16 g_qkB[(size_t)BB * 256 * NN]; // dwconv q,k out (bf16)
__device__ __half        g_vB [(size_t)BB * CC * NN];  // dwconv v out (fp16)
__device__ float g_gram[BB * 8 * 16 * 16];
__device__ float g_ssq [BB * 2 * CC];
__device__ float g_W   [BB * CC * CC];

__device__ __forceinline__ unsigned pbf(float lo, float hi) {
    __nv_bfloat162 h = __floats2bfloat162_rn(lo, hi);
    return *(unsigned*)&h;
}
__device__ __forceinline__ unsigned ph(float lo, float hi) {
    __half2 h = __floats2half2_rn(lo, hi);
    return *(unsigned*)&h;
}
__device__ __forceinline__ void mma16816bf(float* d, const unsigned* a, const unsigned* b) {
    asm volatile("mma.sync.aligned.m16n8k16.row.col.f32.bf16.bf16.f32 "
                 "{%0,%1,%2,%3}, {%4,%5,%6,%7}, {%8,%9}, {%0,%1,%2,%3};"
                 : "+f"(d[0]), "+f"(d[1]), "+f"(d[2]), "+f"(d[3])
                 : "r"(a[0]), "r"(a[1]), "r"(a[2]), "r"(a[3]), "r"(b[0]), "r"(b[1]));
}
__device__ __forceinline__ void mma16816h(float* d, const unsigned* a, const unsigned* b) {
    asm volatile("mma.sync.aligned.m16n8k16.row.col.f32.f16.f16.f32 "
                 "{%0,%1,%2,%3}, {%4,%5,%6,%7}, {%8,%9}, {%0,%1,%2,%3};"
                 : "+f"(d[0]), "+f"(d[1]), "+f"(d[2]), "+f"(d[3])
                 : "r"(a[0]), "r"(a[1]), "r"(a[2]), "r"(a[3]), "r"(b[0]), "r"(b[1]));
}
__device__ __forceinline__ void ldmx4(unsigned* r, unsigned addr) {
    asm volatile("ldmatrix.sync.aligned.m8n8.x4.shared.b16 {%0,%1,%2,%3}, [%4];"
                 : "=r"(r[0]), "=r"(r[1]), "=r"(r[2]), "=r"(r[3]) : "r"(addr));
}

__global__ void zero_k() {
    int t = blockIdx.x * 256 + threadIdx.x;
    if (t < BB * 8 * 16 * 16) g_gram[t] = 0.f;
    if (t < BB * 2 * CC)      g_ssq[t]  = 0.f;
}

// ------ bf16 GEMM for q,k rows (round-11 proven) --------------------------------
__global__ __launch_bounds__(256, 2) void gemm_qk16(
    const float* __restrict__ A,
    const float* __restrict__ B, long long bBatch,
    __nv_bfloat16* __restrict__ C)
{
    extern __shared__ unsigned smu[];
    unsigned* sB = smu;                // [64][136]
    unsigned* sA = smu + 64 * 136;     // [2][128][20]
    const int tid = threadIdx.x;
    const int bn = blockIdx.x, bb = blockIdx.y;
    const float* Bb = B + (long long)bb * bBatch + (long long)bn * 128;
    __nv_bfloat16* Cb = C + (long long)bb * 256 * NN + (long long)bn * 128;

    {
        const int k2r = tid >> 5, nq = tid & 31;
        #pragma unroll
        for (int g = 0; g < 8; g++) {
            int k2 = g * 8 + k2r;
            const float* r0 = Bb + (long long)(2 * k2) * NN + nq * 4;
            float4 v0 = *(const float4*)r0;
            float4 v1 = *(const float4*)(r0 + NN);
            *(uint4*)&sB[k2 * 136 + nq * 4] = make_uint4(
                pbf(v0.x, v1.x), pbf(v0.y, v1.y), pbf(v0.z, v1.z), pbf(v0.w, v1.w));
        }
    }

    const int ar4 = tid >> 2, aq = tid & 3;
    float4 rgf[4];
    auto ldA = [&](int mt, int kt) {
        const float* At = A + (long long)mt * 16384;
        #pragma unroll
        for (int j = 0; j < 2; j++) {
            const float* p = At + (ar4 + 64 * j) * 128 + kt * 32 + aq * 8;
            rgf[2 * j]     = *(const float4*)p;
            rgf[2 * j + 1] = *(const float4*)(p + 4);
        }
    };
    auto stA = [&](int bufsel) {
        unsigned* base = sA + bufsel * 128 * 20;
        #pragma unroll
        for (int j = 0; j < 2; j++) {
            int m = ar4 + 64 * j;
            float4 u = rgf[2 * j], w = rgf[2 * j + 1];
            *(uint4*)&base[m * 20 + aq * 4] = make_uint4(
                pbf(u.x, u.y), pbf(u.z, u.w), pbf(w.x, w.y), pbf(w.z, w.w));
        }
    };

    ldA(0, 0);
    stA(0);
    __syncthreads();

    const int warp = tid >> 5, lane = tid & 31;
    const int wm = warp >> 2, wn = warp & 3;
    const int lr = lane >> 2, lc = lane & 3;

    int buf = 0;
    float acc[4][4][4];
    for (int step = 0; step < 8; step++) {
        const int mt = step >> 2, kt = step & 3;
        if (kt == 0) {
            #pragma unroll
            for (int a = 0; a < 4; a++)
                #pragma unroll
                for (int b2 = 0; b2 < 4; b2++)
                    #pragma unroll
                    for (int r = 0; r < 4; r++) acc[a][b2][r] = 0.f;
        }
        const bool hasNext = (step + 1 < 8);
        if (hasNext) ldA((step + 1) >> 2, (step + 1) & 3);

        const unsigned* sAb = sA + buf * 128 * 20;
        #pragma unroll
        for (int ks = 0; ks < 2; ks++) {
            const int kq = ks * 8;
            const int k2b = kt * 16 + ks * 8;
            unsigned af[4][4], bfr[4][2];
            #pragma unroll
            for (int mi = 0; mi < 4; mi++) {
                int m0 = wm * 64 + mi * 16;
                af[mi][0] = sAb[(m0 + lr) * 20 + kq + lc];
                af[mi][1] = sAb[(m0 + 8 + lr) * 20 + kq + lc];
                af[mi][2] = sAb[(m0 + lr) * 20 + kq + 4 + lc];
                af[mi][3] = sAb[(m0 + 8 + lr) * 20 + kq + 4 + lc];
            }
            #pragma unroll
            for (int ni = 0; ni < 4; ni++) {
                int n0 = wn * 32 + ni * 8;
                bfr[ni][0] = sB[(k2b + lc) * 136 + n0 + lr];
                bfr[ni][1] = sB[(k2b + 4 + lc) * 136 + n0 + lr];
            }
            #pragma unroll
            for (int mi = 0; mi < 4; mi++)
                #pragma unroll
                for (int ni = 0; ni < 4; ni++)
                    mma16816bf(acc[mi][ni], af[mi], bfr[ni]);
        }
        if (hasNext) stA(buf ^ 1);
        __syncthreads();
        buf ^= 1;

        if (kt == 3) {
            #pragma unroll
            for (int mi = 0; mi < 4; mi++) {
                int m0 = mt * 128 + wm * 64 + mi * 16;
                #pragma unroll
                for (int ni = 0; ni < 4; ni++) {
                    int n0 = wn * 32 + ni * 8;
                    __nv_bfloat162 b0 = __float22bfloat162_rn(
                        make_float2(acc[mi][ni][0], acc[mi][ni][1]));
                    __nv_bfloat162 b1 = __float22bfloat162_rn(
                        make_float2(acc[mi][ni][2], acc[mi][ni][3]));
                    *(__nv_bfloat162*)(Cb + (long long)(m0 + lr) * NN + n0 + lc * 2) = b0;
                    *(__nv_bfloat162*)(Cb + (long long)(m0 + 8 + lr) * NN + n0 + lc * 2) = b1;
                }
            }
        }
    }
}

// ------ fp16 GEMM (single 128-row tile): C = A[128,128] @ B[128, NN-tile] --------
// BHALF: B source is fp16 (else fp32, cvt at staging). CHALF: C out fp16 (else fp32).
template <int BHALF, int CHALF>
__global__ __launch_bounds__(256, 2) void gemm_h16(
    const float* __restrict__ A, long long aBatch,
    const void* __restrict__ B, long long bBatch,
    void* __restrict__ C, long long cBatch)
{
    extern __shared__ unsigned smu[];
    unsigned* sB = smu;                // [64][136]
    unsigned* sA = smu + 64 * 136;     // [2][128][20]
    const int tid = threadIdx.x;
    const int bn = blockIdx.x, bb = blockIdx.y;
    const float* Ab = A + (long long)bb * aBatch;

    // ---- stage B as k-pair packed fp16 ----
    {
        const int k2r = tid >> 5, nq = tid & 31;
        #pragma unroll
        for (int g = 0; g < 8; g++) {
            int k2 = g * 8 + k2r;
            if (BHALF) {
                const __half* Bb = (const __half*)B + (long long)bb * bBatch
                                 + (long long)bn * 128;
                const uint2* r0 = (const uint2*)(Bb + (long long)(2 * k2) * NN + nq * 4);
                const uint2* r1 = (const uint2*)(Bb + (long long)(2 * k2 + 1) * NN + nq * 4);
                uint2 u = *r0, v = *r1;
                *(uint4*)&sB[k2 * 136 + nq * 4] = make_uint4(
                    __byte_perm(u.x, v.x, 0x5410), __byte_perm(u.x, v.x, 0x7632),
                    __byte_perm(u.y, v.y, 0x5410), __byte_perm(u.y, v.y, 0x7632));
            } else {
                const float* Bb = (const float*)B + (long long)bb * bBatch
                                + (long long)bn * 128;
                const float* r0 = Bb + (long long)(2 * k2) * NN + nq * 4;
                float4 v0 = *(const float4*)r0;
                float4 v1 = *(const float4*)(r0 + NN);
                *(uint4*)&sB[k2 * 136 + nq * 4] = make_uint4(
                    ph(v0.x, v1.x), ph(v0.y, v1.y), ph(v0.z, v1.z), ph(v0.w, v1.w));
            }
        }
    }

    const int ar4 = tid >> 2, aq = tid & 3;
    float4 rgf[4];
    auto ldA = [&](int kt) {
        #pragma unroll
        for (int j = 0; j < 2; j++) {
            const float* p = Ab + (ar4 + 64 * j) * 128 + kt * 32 + aq * 8;
            rgf[2 * j]     = *(const float4*)p;
            rgf[2 * j + 1] = *(const float4*)(p + 4);
        }
    };
    auto stA = [&](int bufsel) {
        unsigned* base = sA + bufsel * 128 * 20;
        #pragma unroll
        for (int j = 0; j < 2; j++) {
            int m = ar4 + 64 * j;
            float4 u = rgf[2 * j], w = rgf[2 * j + 1];
            *(uint4*)&base[m * 20 + aq * 4] = make_uint4(
                ph(u.x, u.y), ph(u.z, u.w), ph(w.x, w.y), ph(w.z, w.w));
        }
    };

    ldA(0);
    stA(0);
    __syncthreads();

    const int warp = tid >> 5, lane = tid & 31;
    const int wm = warp >> 2, wn = warp & 3;
    const int lr = lane >> 2, lc = lane & 3;

    int buf = 0;
    float acc[4][4][4];
    #pragma unroll
    for (int a = 0; a < 4; a++)
        #pragma unroll
        for (int b2 = 0; b2 < 4; b2++)
            #pragma unroll
            for (int r = 0; r < 4; r++) acc[a][b2][r] = 0.f;

    for (int kt = 0; kt < 4; kt++) {
        const bool hasNext = (kt + 1 < 4);
        if (hasNext) ldA(kt + 1);

        const unsigned* sAb = sA + buf * 128 * 20;
        #pragma unroll
        for (int ks = 0; ks < 2; ks++) {
            const int kq = ks * 8;
            const int k2b = kt * 16 + ks * 8;
            unsigned af[4][4], bfr[4][2];
            #pragma unroll
            for (int mi = 0; mi < 4; mi++) {
                int m0 = wm * 64 + mi * 16;
                af[mi][0] = sAb[(m0 + lr) * 20 + kq + lc];
                af[mi][1] = sAb[(m0 + 8 + lr) * 20 + kq + lc];
                af[mi][2] = sAb[(m0 + lr) * 20 + kq + 4 + lc];
                af[mi][3] = sAb[(m0 + 8 + lr) * 20 + kq + 4 + lc];
            }
            #pragma unroll
            for (int ni = 0; ni < 4; ni++) {
                int n0 = wn * 32 + ni * 8;
                bfr[ni][0] = sB[(k2b + lc) * 136 + n0 + lr];
                bfr[ni][1] = sB[(k2b + 4 + lc) * 136 + n0 + lr];
            }
            #pragma unroll
            for (int mi = 0; mi < 4; mi++)
                #pragma unroll
                for (int ni = 0; ni < 4; ni++)
                    mma16816h(acc[mi][ni], af[mi], bfr[ni]);
        }
        if (hasNext) stA(buf ^ 1);
        __syncthreads();
        buf ^= 1;
    }

    #pragma unroll
    for (int mi = 0; mi < 4; mi++) {
        int m0 = wm * 64 + mi * 16;
        #pragma unroll
        for (int ni = 0; ni < 4; ni++) {
            int n0 = wn * 32 + ni * 8;
            long long r0 = (long long)(m0 + lr) * NN + n0 + lc * 2;
            long long r1 = (long long)(m0 + 8 + lr) * NN + n0 + lc * 2;
            if (CHALF) {
                __half* Cb = (__half*)C + (long long)bb * cBatch + (long long)bn * 128;
                *(__half2*)(Cb + r0) = __floats2half2_rn(acc[mi][ni][0], acc[mi][ni][1]);
                *(__half2*)(Cb + r1) = __floats2half2_rn(acc[mi][ni][2], acc[mi][ni][3]);
            } else {
                float* Cb = (float*)C + (long long)bb * cBatch + (long long)bn * 128;
                *(float2*)(Cb + r0) = make_float2(acc[mi][ni][0], acc[mi][ni][1]);
                *(float2*)(Cb + r1) = make_float2(acc[mi][ni][2], acc[mi][ni][3]);
            }
        }
    }
}

// ------ depthwise 3x3x3 scalar sliding-window (round-15 proven) -----------------
__global__ __launch_bounds__(192, 4) void dwconv_k(
    const __nv_bfloat16* __restrict__ qk_in, const __half* __restrict__ v_in,
    const float* __restrict__ wg,
    __nv_bfloat16* __restrict__ qk_out, __half* __restrict__ v_out)
{
    __shared__ float sP[4][50 * 60];
    __shared__ float sred[192];
    const int hhalf = blockIdx.x, ch = blockIdx.y, b = blockIdx.z;
    const int tx = threadIdx.x, ty = threadIdx.y;
    const int tid = ty * 48 + tx;
    const int h0 = hhalf * 24;
    const bool isQK = (ch < 256);

    for (int i = tid; i < 4 * 3000; i += 192) ((float*)sP)[i] = 0.f;

    float wv[27];
    {
        const float* wp = wg + ch * 27;
        #pragma unroll
        for (int i = 0; i < 27; i++) wv[i] = wp[i];
    }
    __syncthreads();

    const __nv_bfloat16* qbase = qk_in + (long long)(b * 256 + ch) * 48 * 2304;
    const __half* vbase = v_in + (long long)(b * CC + (ch - 256)) * 48 * 2304;

    auto loadPlane = [&](int slot, int hh) {
        float* sp = sP[slot];
        if (isQK) {
            const __nv_bfloat162* pl = (const __nv_bfloat162*)(qbase + (long long)hh * 2304);
            #pragma unroll
            for (int j = 0; j < 6; j++) {
                int l = j * 192 + tid;
                int wr = l / 24, cp = l % 24;
                float2 f = __bfloat1622float2(pl[l]);
                *(float2*)(&sp[(wr + 1) * 60 + 4 + cp * 2]) = f;
            }
        } else {
            const __half2* pl = (const __half2*)(vbase + (long long)hh * 2304);
            #pragma unroll
            for (int j = 0; j < 6; j++) {
                int l = j * 192 + tid;
                int wr = l / 24, cp = l % 24;
                float2 f = __half22float2(pl[l]);
                *(float2*)(&sp[(wr + 1) * 60 + 4 + cp * 2]) = f;
            }
        }
    };
    auto zeroPlane = [&](int slot) {
        float* sp = sP[slot];
        for (int i = tid; i < 3000; i += 192) sp[i] = 0.f;
    };

    if (h0 - 1 >= 0) loadPlane(h0 & 3, h0 - 1);
    loadPlane((h0 + 1) & 3, h0);

    const int d = tx, w0 = ty * 12;
    float lssq = 0.f;
    __nv_bfloat16* qob0 = qk_out + (long long)(b * 256 + ch) * 48 * 2304;
    __half* vob0 = v_out + (long long)(b * CC + (ch - 256)) * 48 * 2304;

    for (int h = h0; h < h0 + 24; h++) {
        if (h + 1 < 48) loadPlane((h + 2) & 3, h + 1);
        else            zeroPlane((h + 2) & 3);
        __syncthreads();
        const float* P0 = sP[h & 3];
        const float* P1 = sP[(h + 1) & 3];
        const float* P2 = sP[(h + 2) & 3];

        float r[3][3][3];
        #pragma unroll
        for (int dp = 0; dp < 3; dp++) {
            r[0][0][dp] = P0[w0 * 60 + d + 3 + dp];
            r[0][1][dp] = P1[w0 * 60 + d + 3 + dp];
            r[0][2][dp] = P2[w0 * 60 + d + 3 + dp];
            r[1][0][dp] = P0[(w0 + 1) * 60 + d + 3 + dp];
            r[1][1][dp] = P1[(w0 + 1) * 60 + d + 3 + dp];
            r[1][2][dp] = P2[(w0 + 1) * 60 + d + 3 + dp];
        }
        const long long rowoff = (long long)h * 2304;
        #pragma unroll
        for (int k = 0; k < 12; k++) {
            const int ns = (k + 2) % 3;
            #pragma unroll
            for (int dp = 0; dp < 3; dp++) {
                r[ns][0][dp] = P0[(w0 + k + 2) * 60 + d + 3 + dp];
                r[ns][1][dp] = P1[(w0 + k + 2) * 60 + d + 3 + dp];
                r[ns][2][dp] = P2[(w0 + k + 2) * 60 + d + 3 + dp];
            }
            float o = 0.f;
            #pragma unroll
            for (int hp = 0; hp < 3; hp++)
                #pragma unroll
                for (int q = 0; q < 3; q++) {
                    const int sl = (k + q) % 3;
                    #pragma unroll
                    for (int dp = 0; dp < 3; dp++)
                        o += wv[hp * 9 + q * 3 + dp] * r[sl][hp][dp];
                }
            const long long off = rowoff + (w0 + k) * 48 + d;
            if (isQK) {
                __nv_bfloat16 bh = __float2bfloat16_rn(o);
                float orr = __bfloat162float(bh);
                lssq += orr * orr;
                qob0[off] = bh;
            } else {
                vob0[off] = __float2half_rn(o);
            }
        }
    }

    if (isQK) {
        sred[tid] = lssq;
        __syncthreads();
        if (tid < 32) {
            float v = sred[tid] + sred[tid + 32] + sred[tid + 64]
                    + sred[tid + 96] + sred[tid + 128] + sred[tid + 160];
            #pragma unroll
            for (int off = 16; off > 0; off >>= 1)
                v += __shfl_down_sync(0xffffffffu, v, off);
            if (tid == 0) atomicAdd(&g_ssq[b * 256 + ch], v);
        }
    }
}

// ------ Gram via bf16 tensor cores (round-7 proven) -----------------------------
__global__ __launch_bounds__(256) void gram_k(const __nv_bfloat16* __restrict__ qk) {
    __shared__ __nv_bfloat16 sq[256 * 40];
    const int tid = threadIdx.x;
    const int b = blockIdx.y;
    const int warp = tid >> 5, lane = tid & 31;
    const int lr4 = lane >> 3, lq = lane & 7;
    const __nv_bfloat16* qkb = qk + (long long)b * 256 * NN;

    uint2 rg[8];
    auto ldC = [&](int c) {
        long long n0 = (long long)c * 32;
        #pragma unroll
        for (int j = 0; j < 8; j++) {
            int row = warp * 32 + j * 4 + lr4;
            rg[j] = *(const uint2*)(qkb + (long long)row * NN + n0 + lq * 4);
        }
    };
    auto stC = [&]() {
        #pragma unroll
        for (int j = 0; j < 8; j++) {
            int row = warp * 32 + j * 4 + lr4;
            *(uint2*)(&sq[row * 40 + lq * 4]) = rg[j];
        }
    };

    const int h = warp;
    const int aRow = h * 16 + (lane & 7) + ((lane >> 3) & 1) * 8;
    const unsigned aAddr = (unsigned)__cvta_generic_to_shared(&sq[aRow * 40])
                         + ((lane >> 4) & 1) * 16;
    const int bRow = 128 + h * 16 + (lane & 7) + ((lane >> 4) & 1) * 8;
    const unsigned bAddr = (unsigned)__cvta_generic_to_shared(&sq[bRow * 40])
                         + ((lane >> 3) & 1) * 16;

    float acc[2][4];
    #pragma unroll
    for (int jh = 0; jh < 2; jh++)
        #pragma unroll
        for (int r = 0; r < 4; r++) acc[jh][r] = 0.f;

    int c = blockIdx.x;
    ldC(c);
    while (1) {
        stC();
        __syncthreads();
        int cn = c + GRB;
        bool more = cn < NN / 32;
        if (more) ldC(cn);
        #pragma unroll
        for (int ks = 0; ks < 2; ks++) {
            unsigned a[4], bb2[4];
            ldmx4(a, aAddr + ks * 32);
            ldmx4(bb2, bAddr + ks * 32);
            mma16816bf(acc[0], a, bb2 + 0);
            mma16816bf(acc[1], a, bb2 + 2);
        }
        __syncthreads();
        if (!more) break;
        c = cn;
    }

    const int row = lane >> 2, col = (lane & 3) * 2;
    float* G = &g_gram[(b * 8 + h) * 256];
    #pragma unroll
    for (int jh = 0; jh < 2; jh++) {
        const int j0 = jh * 8 + col;
        atomicAdd(&G[row * 16 + j0],           acc[jh][0]);
        atomicAdd(&G[row * 16 + j0 + 1],       acc[jh][1]);
        atomicAdd(&G[(row + 8) * 16 + j0],     acc[jh][2]);
        atomicAdd(&G[(row + 8) * 16 + j0 + 1], acc[jh][3]);
    }
}

// ------ softmax + W_b = proj_w @ blockdiag(attn_b) ------------------------------
__global__ __launch_bounds__(256) void fold_k(
    const float* __restrict__ proj_w, const float* __restrict__ temp)
{
    __shared__ float sat[8][16][17];
    const int b = blockIdx.x, tid = threadIdx.x;
    if (tid < 128) {
        const int h = tid >> 4, i = tid & 15;
        float nq = fmaxf(sqrtf(g_ssq[b * 256 + h * 16 + i]), 1e-12f);
        float tv = temp[h];
        float row[16];
        float mx = -1e30f;
        #pragma unroll
        for (int j = 0; j < 16; j++) {
            float nk = fmaxf(sqrtf(g_ssq[b * 256 + 128 + h * 16 + j]), 1e-12f);
            float v = g_gram[((b * 8 + h) * 16 + i) * 16 + j] / (nq * nk) * tv;
            row[j] = v;
            mx = fmaxf(mx, v);
        }
        float s = 0.f;
        #pragma unroll
        for (int j = 0; j < 16; j++) { row[j] = expf(row[j] - mx); s += row[j]; }
        const float inv = 1.f / s;
        #pragma unroll
        for (int j = 0; j < 16; j++) sat[h][i][j] = row[j] * inv;
    }
    __syncthreads();
    for (int idx = tid; idx < 16384; idx += 256) {
        const int o = idx >> 7, col = idx & 127;
        const int h = col >> 4, j = col & 15;
        float s = 0.f;
        #pragma unroll
        for (int i = 0; i < 16; i++)
            s += proj_w[o * 128 + h * 16 + i] * sat[h][i][j];
        g_W[b * 16384 + idx] = s;
    }
}

extern "C" void kernel_launch(void* const* d_in, const int* in_sizes, int n_in,
                              void* d_out, int out_size) {
    const float* x      = (const float*)d_in[0];
    const float* qkv_w  = (const float*)d_in[1];
    const float* dw_w   = (const float*)d_in[2];
    const float* proj_w = (const float*)d_in[3];
    const float* temp   = (const float*)d_in[4];
    float* out = (float*)d_out;

    void *p_qkA = nullptr, *p_vA = nullptr, *p_qkB = nullptr, *p_vB = nullptr, *p_W = nullptr;
    cudaGetSymbolAddress(&p_qkA, g_qkA);
    cudaGetSymbolAddress(&p_vA,  g_vA);
    cudaGetSymbolAddress(&p_qkB, g_qkB);
    cudaGetSymbolAddress(&p_vB,  g_vB);
    cudaGetSymbolAddress(&p_W,   g_W);

    cudaFuncSetAttribute(gemm_qk16, cudaFuncAttributeMaxDynamicSharedMemorySize, QK_SMEM);
    cudaFuncSetAttribute((gemm_h16<0, 1>), cudaFuncAttributeMaxDynamicSharedMemorySize, QK_SMEM);
    cudaFuncSetAttribute((gemm_h16<1, 0>), cudaFuncAttributeMaxDynamicSharedMemorySize, QK_SMEM);

    zero_k<<<16, 256>>>();

    // q,k = qkv_w[0:256] @ x  (bf16 MMA, bf16 out)
    gemm_qk16<<<dim3(NN / 128, BB), 256, QK_SMEM>>>(
        qkv_w, x, (long long)CC * NN, (__nv_bfloat16*)p_qkA);

    // v = qkv_w[256:384] @ x  (fp16 MMA, fp16 out)
    gemm_h16<0, 1><<<dim3(NN / 128, BB), 256, QK_SMEM>>>(
        qkv_w + 256 * 128, 0LL,
        x, (long long)CC * NN,
        p_vA, (long long)CC * NN);

    dwconv_k<<<dim3(2, C3, BB), dim3(48, 4)>>>(
        (const __nv_bfloat16*)p_qkA, (const __half*)p_vA, dw_w,
        (__nv_bfloat16*)p_qkB, (__half*)p_vB);

    gram_k<<<dim3(GRB, BB), 256>>>((const __nv_bfloat16*)p_qkB);

    fold_k<<<BB, 256>>>(proj_w, temp);

    // out = W_b @ v  (fp16 MMA: W cvt fp16, vB fp16 in, fp32 out)
    gemm_h16<1, 0><<<dim3(NN / 128, BB), 256, QK_SMEM>>>(
        (const float*)p_W, (long long)CC * CC,
        p_vB, (long long)CC * NN,
        out, (long long)CC * NN);
}